// round 2
// baseline (speedup 1.0000x reference)
#include <cuda_runtime.h>
#include <math_constants.h>

#define N_NODES 50000
#define N_EDGES 800000
#define EDGE_F  96
#define NODE_F  256
#define GLOB_F  64
#define HIDDEN  1024
#define MLP_IN  608   // 256 + 3*96 + 64

// Scratch (device globals: allocation-free per harness rules)
__device__ float g_h [(size_t)N_NODES * MLP_IN];   // composed MLP input [N,608]
__device__ float g_h1[(size_t)N_NODES * HIDDEN];   // hidden activations [N,1024]
__device__ int   g_cnt[N_NODES];

// ---------------------------------------------------------------------------
// Init: x -> cols [0,256); 0 -> sum [256,352); -inf -> max [352,448);
// 0 -> mean [448,544); u[batch] -> [544,608). Zero counts.
// One thread per float4 of a row (608/4 = 152 per node).
// ---------------------------------------------------------------------------
__global__ void init_kernel(const float* __restrict__ x,
                            const float* __restrict__ u,
                            const int*   __restrict__ batch)
{
    int i = blockIdx.x * blockDim.x + threadIdx.x;
    if (i >= N_NODES * 152) return;
    int n = i / 152;
    int q = i - n * 152;           // float4 index within row, col = 4*q

    float4 v;
    if (q < 64) {                  // x
        v = ((const float4*)(x + (size_t)n * NODE_F))[q];
    } else if (q < 88) {           // sum -> 0
        v = make_float4(0.f, 0.f, 0.f, 0.f);
    } else if (q < 112) {          // max -> -inf
        float ninf = __int_as_float(0xff800000);
        v = make_float4(ninf, ninf, ninf, ninf);
    } else if (q < 136) {          // mean -> 0
        v = make_float4(0.f, 0.f, 0.f, 0.f);
    } else {                       // u[batch[n]]
        int b = batch[n];
        v = ((const float4*)(u + (size_t)b * GLOB_F))[q - 136];
    }
    ((float4*)(g_h + (size_t)n * MLP_IN))[q] = v;
    if (q == 0) g_cnt[n] = 0;
}

// ---------------------------------------------------------------------------
// Edge scatter: sum + max atomics. One thread per (edge, float4 of features).
// ---------------------------------------------------------------------------
__device__ __forceinline__ void atomicMaxF(float* addr, float v) {
    // Sign-split trick; no return-value use so ptxas can emit RED.
    if (v >= 0.f) atomicMax((int*)addr, __float_as_int(v));
    else          atomicMin((unsigned int*)addr, __float_as_uint(v));
}

__global__ void scatter_kernel(const float* __restrict__ edge_attr,
                               const int*   __restrict__ dst)
{
    int i = blockIdx.x * blockDim.x + threadIdx.x;   // over N_EDGES*24
    if (i >= N_EDGES * (EDGE_F / 4)) return;
    int e = i / (EDGE_F / 4);
    int q = i - e * (EDGE_F / 4);                    // float4 index, f = 4q
    int c = dst[e];
    float4 v = ((const float4*)(edge_attr + (size_t)e * EDGE_F))[q];
    float* sumb = g_h + (size_t)c * MLP_IN + 256 + 4 * q;
    float* maxb = g_h + (size_t)c * MLP_IN + 352 + 4 * q;
    atomicAdd(sumb + 0, v.x);
    atomicAdd(sumb + 1, v.y);
    atomicAdd(sumb + 2, v.z);
    atomicAdd(sumb + 3, v.w);
    atomicMaxF(maxb + 0, v.x);
    atomicMaxF(maxb + 1, v.y);
    atomicMaxF(maxb + 2, v.z);
    atomicMaxF(maxb + 3, v.w);
    if (q == 0) atomicAdd(&g_cnt[c], 1);
}

// ---------------------------------------------------------------------------
// Finalize: mean = sum/cnt; empty segments -> max := 0, mean := 0.
// One thread per (node, float4 of the 96 features).
// ---------------------------------------------------------------------------
__global__ void finalize_kernel()
{
    int i = blockIdx.x * blockDim.x + threadIdx.x;   // over N_NODES*24
    if (i >= N_NODES * (EDGE_F / 4)) return;
    int n = i / (EDGE_F / 4);
    int q = i - n * (EDGE_F / 4);
    float* base = g_h + (size_t)n * MLP_IN;
    int cnt = g_cnt[n];
    if (cnt == 0) {
        float4 z = make_float4(0.f, 0.f, 0.f, 0.f);
        ((float4*)(base + 352))[q] = z;   // segment_max of empty -> 0
        ((float4*)(base + 448))[q] = z;   // mean of empty -> 0
    } else {
        float inv = 1.0f / (float)cnt;
        float4 s = ((const float4*)(base + 256))[q];
        float4 m = make_float4(s.x * inv, s.y * inv, s.z * inv, s.w * inv);
        ((float4*)(base + 448))[q] = m;
    }
}

// ---------------------------------------------------------------------------
// SGEMM: C[M,N] = epilogue(A[M,K] @ B[K,N]).
// 128x128 block tile, BK=8, 8x8 per thread, 256 threads.
// EPI=1: relu(acc + bias)            (hidden layer)
// EPI=2: acc + bias + res[row,col]   (output layer + residual)
// Requires K % 8 == 0, N % 128 == 0. M-edge guarded.
// ---------------------------------------------------------------------------
template<int EPI>
__global__ __launch_bounds__(256, 2)
void sgemm128(const float* __restrict__ A, const float* __restrict__ B,
              const float* __restrict__ bias, const float* __restrict__ res,
              float* __restrict__ C, int M, int N, int K)
{
    __shared__ float As[8][128];   // transposed A tile: As[k][m]
    __shared__ float Bs[8][128];

    const int t = threadIdx.x;
    const int rowBase = blockIdx.y * 128;
    const int colBase = blockIdx.x * 128;

    // A tile load: 128 rows x 8 cols, float4 along K.
    const int aRow = t >> 1;            // 0..127
    const int aCol = (t & 1) * 4;       // 0 or 4
    // B tile load: 8 rows x 128 cols, float4 along N.
    const int bRow = t >> 5;            // 0..7
    const int bCol = (t & 31) * 4;      // 0..124

    const int ty = t >> 4;              // 0..15 -> rows ty*8..ty*8+7
    const int tx = t & 15;              // 0..15 -> cols tx*8..tx*8+7

    const bool aValid = (rowBase + aRow) < M;
    const float* Aptr = A + (size_t)(rowBase + aRow) * K + aCol;
    const float* Bptr = B + (size_t)bRow * N + colBase + bCol;

    float acc[8][8];
#pragma unroll
    for (int i = 0; i < 8; ++i)
#pragma unroll
        for (int j = 0; j < 8; ++j) acc[i][j] = 0.f;

    for (int k0 = 0; k0 < K; k0 += 8) {
        float4 av = aValid ? *(const float4*)(Aptr + k0)
                           : make_float4(0.f, 0.f, 0.f, 0.f);
        float4 bv = *(const float4*)(Bptr + (size_t)k0 * N);

        As[aCol + 0][aRow] = av.x;
        As[aCol + 1][aRow] = av.y;
        As[aCol + 2][aRow] = av.z;
        As[aCol + 3][aRow] = av.w;
        *(float4*)&Bs[bRow][bCol] = bv;
        __syncthreads();

#pragma unroll
        for (int kk = 0; kk < 8; ++kk) {
            float a[8], b[8];
            *(float4*)(a)     = *(const float4*)&As[kk][ty * 8];
            *(float4*)(a + 4) = *(const float4*)&As[kk][ty * 8 + 4];
            *(float4*)(b)     = *(const float4*)&Bs[kk][tx * 8];
            *(float4*)(b + 4) = *(const float4*)&Bs[kk][tx * 8 + 4];
#pragma unroll
            for (int i = 0; i < 8; ++i)
#pragma unroll
                for (int j = 0; j < 8; ++j)
                    acc[i][j] = fmaf(a[i], b[j], acc[i][j]);
        }
        __syncthreads();
    }

    // Epilogue
    float bv[8];
#pragma unroll
    for (int j = 0; j < 8; ++j) bv[j] = bias[colBase + tx * 8 + j];

#pragma unroll
    for (int i = 0; i < 8; ++i) {
        int row = rowBase + ty * 8 + i;
        if (row >= M) continue;
        float* cRow = C + (size_t)row * N + colBase + tx * 8;
        float o[8];
        if (EPI == 1) {
#pragma unroll
            for (int j = 0; j < 8; ++j)
                o[j] = fmaxf(acc[i][j] + bv[j], 0.f);
        } else {
            const float* rRow = res + (size_t)row * N + colBase + tx * 8;
            float4 r0 = *(const float4*)(rRow);
            float4 r1 = *(const float4*)(rRow + 4);
            o[0] = acc[i][0] + bv[0] + r0.x;
            o[1] = acc[i][1] + bv[1] + r0.y;
            o[2] = acc[i][2] + bv[2] + r0.z;
            o[3] = acc[i][3] + bv[3] + r0.w;
            o[4] = acc[i][4] + bv[4] + r1.x;
            o[5] = acc[i][5] + bv[5] + r1.y;
            o[6] = acc[i][6] + bv[6] + r1.z;
            o[7] = acc[i][7] + bv[7] + r1.w;
        }
        *(float4*)(cRow)     = make_float4(o[0], o[1], o[2], o[3]);
        *(float4*)(cRow + 4) = make_float4(o[4], o[5], o[6], o[7]);
    }
}

// ---------------------------------------------------------------------------
extern "C" void kernel_launch(void* const* d_in, const int* in_sizes, int n_in,
                              void* d_out, int out_size)
{
    const float* x     = (const float*)d_in[0];
    const float* ea    = (const float*)d_in[1];
    const float* u     = (const float*)d_in[2];
    const float* W1    = (const float*)d_in[3];
    const float* b1    = (const float*)d_in[4];
    const float* W2    = (const float*)d_in[5];
    const float* b2    = (const float*)d_in[6];
    const int*   ei    = (const int*)  d_in[7];   // [2, N_EDGES]; row 1 = dst
    const int*   batch = (const int*)  d_in[8];
    float*       out   = (float*)d_out;

    float *h, *h1;
    cudaGetSymbolAddress((void**)&h,  g_h);
    cudaGetSymbolAddress((void**)&h1, g_h1);

    init_kernel<<<(N_NODES * 152 + 255) / 256, 256>>>(x, u, batch);
    scatter_kernel<<<(N_EDGES * (EDGE_F / 4) + 255) / 256, 256>>>(ea, ei + N_EDGES);
    finalize_kernel<<<(N_NODES * (EDGE_F / 4) + 255) / 256, 256>>>();

    dim3 g1(HIDDEN / 128, (N_NODES + 127) / 128);
    sgemm128<1><<<g1, 256>>>(h, W1, b1, nullptr, h1, N_NODES, HIDDEN, MLP_IN);

    dim3 g2(NODE_F / 128, (N_NODES + 127) / 128);
    sgemm128<2><<<g2, 256>>>(h1, W2, b2, x, out, N_NODES, NODE_F, HIDDEN);
}

// round 4
// speedup vs baseline: 1.9138x; 1.9138x over previous
#include <cuda_runtime.h>
#include <cuda_bf16.h>
#include <cstdint>

#define N_NODES 50000
#define N_EDGES 800000
#define EDGE_F  96
#define NODE_F  256
#define GLOB_F  64
#define HIDDEN  1024
#define K1PAD   640              // 608 padded to multiple of 32
#define MTILES  391
#define MPAD    (MTILES*128)     // 50048

// ---------------- device scratch (allocation-free per harness rules) -------
__device__ float g_agg[(size_t)N_NODES*192];       // sum[0:96), max[96:192)
__device__ int   g_cnt[N_NODES];
__device__ __nv_bfloat16 g_Ah[(size_t)MPAD*K1PAD];
__device__ __nv_bfloat16 g_Al[(size_t)MPAD*K1PAD];
__device__ __nv_bfloat16 g_Hh[(size_t)MPAD*HIDDEN];
__device__ __nv_bfloat16 g_Hl[(size_t)MPAD*HIDDEN];
__device__ __nv_bfloat16 g_B1h[(size_t)HIDDEN*K1PAD];
__device__ __nv_bfloat16 g_B1l[(size_t)HIDDEN*K1PAD];
__device__ __nv_bfloat16 g_B2h[(size_t)NODE_F*HIDDEN];
__device__ __nv_bfloat16 g_B2l[(size_t)NODE_F*HIDDEN];

// ---------------- PTX helpers ----------------------------------------------
__device__ __forceinline__ uint32_t smem_u32(const void* p) {
    uint32_t a;
    asm("{ .reg .u64 t; cvta.to.shared.u64 t, %1; cvt.u32.u64 %0, t; }" : "=r"(a) : "l"(p));
    return a;
}
#define CPASYNC16(s,g) asm volatile("cp.async.cg.shared.global [%0], [%1], 16;" :: "r"(s), "l"(g))
#define CPCOMMIT()     asm volatile("cp.async.commit_group;" ::: "memory")
#define CPWAIT2()      asm volatile("cp.async.wait_group 2;" ::: "memory")

#define LDSM4(r0,r1,r2,r3,addr) \
    asm volatile("ldmatrix.sync.aligned.m8n8.x4.shared.b16 {%0,%1,%2,%3}, [%4];" \
        : "=r"(r0),"=r"(r1),"=r"(r2),"=r"(r3) : "r"(addr))

#define MMA16816(d,a,b0,b1) \
    asm volatile("mma.sync.aligned.m16n8k16.row.col.f32.bf16.bf16.f32 " \
        "{%0,%1,%2,%3}, {%4,%5,%6,%7}, {%8,%9}, {%0,%1,%2,%3};" \
        : "+f"((d)[0]),"+f"((d)[1]),"+f"((d)[2]),"+f"((d)[3]) \
        : "r"((a)[0]),"r"((a)[1]),"r"((a)[2]),"r"((a)[3]), "r"(b0),"r"(b1))

__device__ __forceinline__ uint32_t pk_hi(float a, float b) {
    return (uint32_t)__bfloat16_as_ushort(__float2bfloat16(a))
         | ((uint32_t)__bfloat16_as_ushort(__float2bfloat16(b)) << 16);
}
__device__ __forceinline__ float bf_res(float v) {   // v - bf16(v)
    return v - __bfloat162float(__float2bfloat16(v));
}

// ---------------- phase 1: segment reductions -------------------------------
__global__ void init_agg() {
    int i = blockIdx.x * blockDim.x + threadIdx.x;      // N_NODES*48 float4s
    if (i >= N_NODES * 48) return;
    int n = i / 48, q = i - n * 48;
    float4* row = (float4*)(g_agg + (size_t)n * 192);
    if (q < 24) row[q] = make_float4(0.f, 0.f, 0.f, 0.f);
    else {
        float ninf = __int_as_float(0xff800000);
        row[q] = make_float4(ninf, ninf, ninf, ninf);
    }
    if (q == 0) g_cnt[n] = 0;
}

__device__ __forceinline__ void atomicMaxF(float* addr, float v) {
    if (v >= 0.f) atomicMax((int*)addr, __float_as_int(v));
    else          atomicMin((unsigned int*)addr, __float_as_uint(v));
}

__global__ void scatter_kernel(const float* __restrict__ ea, const int* __restrict__ dst) {
    int i = blockIdx.x * blockDim.x + threadIdx.x;      // N_EDGES*24
    if (i >= N_EDGES * 24) return;
    int e = i / 24, q = i - e * 24;
    int c = dst[e];
    float4 v = ((const float4*)(ea + (size_t)e * EDGE_F))[q];
    float* s = g_agg + (size_t)c * 192 + 4 * q;
    atomicAdd(s + 0, v.x);  atomicAdd(s + 1, v.y);
    atomicAdd(s + 2, v.z);  atomicAdd(s + 3, v.w);
    atomicMaxF(s + 96 + 0, v.x);  atomicMaxF(s + 96 + 1, v.y);
    atomicMaxF(s + 96 + 2, v.z);  atomicMaxF(s + 96 + 3, v.w);
    if (q == 0) atomicAdd(&g_cnt[c], 1);
}

// compose 608-col MLP input, bf16-split into g_Ah/g_Al, pad to 640/MPAD
__global__ void convert_kernel(const float* __restrict__ x, const float* __restrict__ u,
                               const int* __restrict__ batch) {
    int i = blockIdx.x * blockDim.x + threadIdx.x;      // MPAD*160 tasks (4 cols each)
    if (i >= MPAD * 160) return;
    int n = i / 160, q = i - n * 160;
    float v[4] = {0.f, 0.f, 0.f, 0.f};
    if (n < N_NODES) {
        int cnt = g_cnt[n];
        float inv = cnt > 0 ? 1.f / (float)cnt : 0.f;
#pragma unroll
        for (int t = 0; t < 4; ++t) {
            int c = q * 4 + t;
            float w;
            if (c < 256)      w = x[(size_t)n * NODE_F + c];
            else if (c < 352) w = g_agg[(size_t)n * 192 + (c - 256)];
            else if (c < 448) w = cnt > 0 ? g_agg[(size_t)n * 192 + 96 + (c - 352)] : 0.f;
            else if (c < 544) w = g_agg[(size_t)n * 192 + (c - 448)] * inv;
            else if (c < 608) w = u[(size_t)batch[n] * GLOB_F + (c - 544)];
            else              w = 0.f;
            v[t] = w;
        }
    }
    size_t off = (size_t)n * K1PAD + 4 * q;
    *(uint2*)(g_Ah + off) = make_uint2(pk_hi(v[0], v[1]), pk_hi(v[2], v[3]));
    *(uint2*)(g_Al + off) = make_uint2(pk_hi(bf_res(v[0]), bf_res(v[1])),
                                       pk_hi(bf_res(v[2]), bf_res(v[3])));
}

// transpose + split weights: B1[n][k] = W1[k][n], B2[n][k] = W2[k][n]
__global__ void prep_w(const float* __restrict__ W1, const float* __restrict__ W2) {
    int i = blockIdx.x * blockDim.x + threadIdx.x;
    const int T1 = HIDDEN * 160;
    if (i < T1) {
        int n = i / 160, q = i - n * 160;
        float v[4];
#pragma unroll
        for (int t = 0; t < 4; ++t) {
            int k = 4 * q + t;
            v[t] = (k < 608) ? W1[(size_t)k * HIDDEN + n] : 0.f;
        }
        size_t off = (size_t)n * K1PAD + 4 * q;
        *(uint2*)(g_B1h + off) = make_uint2(pk_hi(v[0], v[1]), pk_hi(v[2], v[3]));
        *(uint2*)(g_B1l + off) = make_uint2(pk_hi(bf_res(v[0]), bf_res(v[1])),
                                            pk_hi(bf_res(v[2]), bf_res(v[3])));
    } else {
        int j = i - T1;
        if (j >= NODE_F * 256) return;
        int n = j / 256, q = j - n * 256;
        float v[4];
#pragma unroll
        for (int t = 0; t < 4; ++t) v[t] = W2[(size_t)(4 * q + t) * NODE_F + n];
        size_t off = (size_t)n * HIDDEN + 4 * q;
        *(uint2*)(g_B2h + off) = make_uint2(pk_hi(v[0], v[1]), pk_hi(v[2], v[3]));
        *(uint2*)(g_B2l + off) = make_uint2(pk_hi(bf_res(v[0]), bf_res(v[1])),
                                            pk_hi(bf_res(v[2]), bf_res(v[3])));
    }
}

// ---------------- phase 2: warp-mma bf16 3-term GEMM -------------------------
// CTA tile 128x128, BK=32. 8 warps in 4(m) x 2(n); warp tile 32x64.
// SMEM stage: Ah[128][32] Al Bh Bl bf16, 8KB each = 32KB; 3 stages = 96KB.
// Swizzle: 16B chunk index ^= (row & 3) within 64B rows -> conflict-free
// for both cp.async stores and ldmatrix loads.
#define STAGE_B 32768

__device__ __forceinline__ void issue_stage(
    uint32_t smemS, const __nv_bfloat16* __restrict__ Ah, const __nv_bfloat16* __restrict__ Al,
    const __nv_bfloat16* __restrict__ Bh, const __nv_bfloat16* __restrict__ Bl,
    int mBase, int cBase, int Kpad, int k0, int tid)
{
#pragma unroll
    for (int j = 0; j < 8; ++j) {
        int t8  = tid + 256 * j;
        int tile = t8 >> 9;
        int idx  = t8 & 511;
        int row  = idx >> 2;
        int ch   = idx & 3;
        uint32_t dst = smemS + tile * 8192 + row * 64 + ((ch ^ (row & 3)) << 4);
        const __nv_bfloat16* src;
        if (tile == 0)      src = Ah + (size_t)(mBase + row) * Kpad + k0 + ch * 8;
        else if (tile == 1) src = Al + (size_t)(mBase + row) * Kpad + k0 + ch * 8;
        else if (tile == 2) src = Bh + (size_t)(cBase + row) * Kpad + k0 + ch * 8;
        else                src = Bl + (size_t)(cBase + row) * Kpad + k0 + ch * 8;
        CPASYNC16(dst, src);
    }
}

template<int EPI>
__global__ __launch_bounds__(256)
void mma_gemm(const __nv_bfloat16* __restrict__ Ah, const __nv_bfloat16* __restrict__ Al,
              const __nv_bfloat16* __restrict__ Bh, const __nv_bfloat16* __restrict__ Bl,
              const float* __restrict__ bias, const float* __restrict__ resid,
              __nv_bfloat16* __restrict__ Oh, __nv_bfloat16* __restrict__ Ol,
              float* __restrict__ outF, int Kpad, int ldo)
{
    extern __shared__ char smem[];
    const uint32_t sb = smem_u32(smem);
    const int tid = threadIdx.x;
    const int wid = tid >> 5, lid = tid & 31;
    const int wm = wid >> 1, wn = wid & 1;          // 4x2 warp grid

    const int mBase = blockIdx.y * 128;
    const int cBase = blockIdx.x * 128;
    const int NC = Kpad >> 5;

    // per-lane ldmatrix address components
    // A: lanes 0-7 rows r..r+7 (khalf0), 8-15 rows+8 (khalf0), 16-23 rows (khalf1), 24-31 rows+8 (khalf1)
    const int aRow = wm * 32 + ((lid >> 3) & 1) * 8 + (lid & 7);   // + msub*16
    const int aK   = (lid >> 4) & 1;
    const int aB   = aRow * 64, aM = aRow & 3;
    // B: lanes 0-7 n..n+7 khalf0, 8-15 same n khalf1, 16-23 n+8 khalf0, 24-31 n+8 khalf1
    const int bRow = wn * 64 + ((lid >> 4) & 1) * 8 + (lid & 7);   // + nb*16
    const int bK   = (lid >> 3) & 1;
    const int bB   = bRow * 64, bM = bRow & 3;

    float acc[2][8][4];
#pragma unroll
    for (int m = 0; m < 2; ++m)
#pragma unroll
        for (int n = 0; n < 8; ++n)
#pragma unroll
            for (int c = 0; c < 4; ++c) acc[m][n][c] = 0.f;

    issue_stage(sb,           Ah, Al, Bh, Bl, mBase, cBase, Kpad, 0,  tid); CPCOMMIT();
    issue_stage(sb + STAGE_B, Ah, Al, Bh, Bl, mBase, cBase, Kpad, 32, tid); CPCOMMIT();

    for (int i = 0; i < NC; ++i) {
        if (i + 2 < NC)
            issue_stage(sb + ((i + 2) % 3) * STAGE_B, Ah, Al, Bh, Bl,
                        mBase, cBase, Kpad, (i + 2) * 32, tid);
        CPCOMMIT();
        CPWAIT2();
        __syncthreads();

        const uint32_t S = sb + (i % 3) * STAGE_B;
#pragma unroll
        for (int ks = 0; ks < 2; ++ks) {
            uint32_t ah[2][4], al[2][4], bh[4][4], bl[4][4];
            const int kcA = ks * 2 + aK;
            const uint32_t offA = ((kcA ^ aM) << 4) + aB;
#pragma unroll
            for (int ms = 0; ms < 2; ++ms) {
                LDSM4(ah[ms][0], ah[ms][1], ah[ms][2], ah[ms][3], S + offA + ms * 1024);
                LDSM4(al[ms][0], al[ms][1], al[ms][2], al[ms][3], S + 8192 + offA + ms * 1024);
            }
            const int kcB = ks * 2 + bK;
            const uint32_t offB = ((kcB ^ bM) << 4) + bB;
#pragma unroll
            for (int nb = 0; nb < 4; ++nb) {
                LDSM4(bh[nb][0], bh[nb][1], bh[nb][2], bh[nb][3], S + 16384 + offB + nb * 1024);
                LDSM4(bl[nb][0], bl[nb][1], bl[nb][2], bl[nb][3], S + 24576 + offB + nb * 1024);
            }
#pragma unroll
            for (int ms = 0; ms < 2; ++ms)
#pragma unroll
                for (int ns = 0; ns < 8; ++ns) {
                    const int nb = ns >> 1, h = (ns & 1) * 2;
                    MMA16816(acc[ms][ns], ah[ms], bh[nb][h], bh[nb][h + 1]);
                    MMA16816(acc[ms][ns], ah[ms], bl[nb][h], bl[nb][h + 1]);
                    MMA16816(acc[ms][ns], al[ms], bh[nb][h], bh[nb][h + 1]);
                }
        }
        __syncthreads();
    }

    // ---------------- epilogue ----------------
    const int l4 = lid >> 2, l2 = (lid & 3) * 2;
#pragma unroll
    for (int ms = 0; ms < 2; ++ms) {
        const int r0 = mBase + wm * 32 + ms * 16 + l4;
        const int r1 = r0 + 8;
#pragma unroll
        for (int ns = 0; ns < 8; ++ns) {
            const int col = cBase + wn * 64 + ns * 8 + l2;
            const float b0 = __ldg(&bias[col]), b1 = __ldg(&bias[col + 1]);
            float v00 = acc[ms][ns][0] + b0, v01 = acc[ms][ns][1] + b1;
            float v10 = acc[ms][ns][2] + b0, v11 = acc[ms][ns][3] + b1;
            if (EPI == 1) {
                v00 = fmaxf(v00, 0.f); v01 = fmaxf(v01, 0.f);
                v10 = fmaxf(v10, 0.f); v11 = fmaxf(v11, 0.f);
                *(uint32_t*)(Oh + (size_t)r0 * ldo + col) = pk_hi(v00, v01);
                *(uint32_t*)(Ol + (size_t)r0 * ldo + col) = pk_hi(bf_res(v00), bf_res(v01));
                *(uint32_t*)(Oh + (size_t)r1 * ldo + col) = pk_hi(v10, v11);
                *(uint32_t*)(Ol + (size_t)r1 * ldo + col) = pk_hi(bf_res(v10), bf_res(v11));
            } else {
                if (r0 < N_NODES) {
                    const float* xr = resid + (size_t)r0 * NODE_F + col;
                    *(float2*)(outF + (size_t)r0 * ldo + col) =
                        make_float2(v00 + xr[0], v01 + xr[1]);
                }
                if (r1 < N_NODES) {
                    const float* xr = resid + (size_t)r1 * NODE_F + col;
                    *(float2*)(outF + (size_t)r1 * ldo + col) =
                        make_float2(v10 + xr[0], v11 + xr[1]);
                }
            }
        }
    }
}

// ---------------------------------------------------------------------------
extern "C" void kernel_launch(void* const* d_in, const int* in_sizes, int n_in,
                              void* d_out, int out_size) {
    const float* x     = (const float*)d_in[0];
    const float* ea    = (const float*)d_in[1];
    const float* u     = (const float*)d_in[2];
    const float* W1    = (const float*)d_in[3];
    const float* b1    = (const float*)d_in[4];
    const float* W2    = (const float*)d_in[5];
    const float* b2    = (const float*)d_in[6];
    const int*   ei    = (const int*)  d_in[7];   // [2, N_EDGES]; row 1 = dst
    const int*   batch = (const int*)  d_in[8];
    float*       out   = (float*)d_out;

    __nv_bfloat16 *Ah, *Al, *Hh, *Hl, *B1h, *B1l, *B2h, *B2l;
    cudaGetSymbolAddress((void**)&Ah,  g_Ah);
    cudaGetSymbolAddress((void**)&Al,  g_Al);
    cudaGetSymbolAddress((void**)&Hh,  g_Hh);
    cudaGetSymbolAddress((void**)&Hl,  g_Hl);
    cudaGetSymbolAddress((void**)&B1h, g_B1h);
    cudaGetSymbolAddress((void**)&B1l, g_B1l);
    cudaGetSymbolAddress((void**)&B2h, g_B2h);
    cudaGetSymbolAddress((void**)&B2l, g_B2l);

    const int SMEM_SZ = 3 * STAGE_B;
    static bool attrDone = false;
    if (!attrDone) {
        cudaFuncSetAttribute(mma_gemm<1>, cudaFuncAttributeMaxDynamicSharedMemorySize, SMEM_SZ);
        cudaFuncSetAttribute(mma_gemm<2>, cudaFuncAttributeMaxDynamicSharedMemorySize, SMEM_SZ);
        attrDone = true;
    }

    init_agg<<<(N_NODES * 48 + 255) / 256, 256>>>();
    prep_w<<<(HIDDEN * 160 + NODE_F * 256 + 255) / 256, 256>>>(W1, W2);
    scatter_kernel<<<(N_EDGES * 24 + 255) / 256, 256>>>(ea, ei + N_EDGES);
    convert_kernel<<<(MPAD * 160 + 255) / 256, 256>>>(x, u, batch);

    mma_gemm<1><<<dim3(HIDDEN / 128, MTILES), 256, SMEM_SZ>>>(
        Ah, Al, B1h, B1l, b1, nullptr, Hh, Hl, nullptr, K1PAD, HIDDEN);
    mma_gemm<2><<<dim3(NODE_F / 128, MTILES), 256, SMEM_SZ>>>(
        Hh, Hl, B2h, B2l, b2, x, nullptr, nullptr, out, HIDDEN, NODE_F);
}

// round 7
// speedup vs baseline: 2.4086x; 1.2585x over previous
#include <cuda_runtime.h>
#include <cuda_bf16.h>
#include <cstdint>

#define N_NODES 50000
#define N_EDGES 800000
#define EDGE_F  96
#define NODE_F  256
#define GLOB_F  64
#define HIDDEN  1024
#define K1PAD   640              // 608 padded to multiple of 32
#define MTILES  391
#define MPAD    (MTILES*128)     // 50048

// ---------------- device scratch (allocation-free per harness rules) -------
__device__ float g_agg[(size_t)N_NODES*192];       // sum[0:96), max[96:192)
__device__ int   g_cnt[N_NODES];                   // counts, then fill-cursor
__device__ int   g_start[N_NODES + 1];             // CSR offsets (+sentinel)
__device__ int   g_eidx[N_EDGES];
__device__ __nv_bfloat16 g_Ah[(size_t)MPAD*K1PAD];
__device__ __nv_bfloat16 g_Al[(size_t)MPAD*K1PAD];
__device__ __nv_bfloat16 g_Hh[(size_t)MPAD*HIDDEN];
__device__ __nv_bfloat16 g_Hl[(size_t)MPAD*HIDDEN];
__device__ __nv_bfloat16 g_B1h[(size_t)HIDDEN*K1PAD];
__device__ __nv_bfloat16 g_B1l[(size_t)HIDDEN*K1PAD];
__device__ __nv_bfloat16 g_B2h[(size_t)NODE_F*HIDDEN];
__device__ __nv_bfloat16 g_B2l[(size_t)NODE_F*HIDDEN];

// ---------------- PTX helpers ----------------------------------------------
__device__ __forceinline__ uint32_t smem_u32(const void* p) {
    uint32_t a;
    asm("{ .reg .u64 t; cvta.to.shared.u64 t, %1; cvt.u32.u64 %0, t; }" : "=r"(a) : "l"(p));
    return a;
}
#define CPASYNC16(s,g) asm volatile("cp.async.cg.shared.global [%0], [%1], 16;" :: "r"(s), "l"(g))
#define CPCOMMIT()     asm volatile("cp.async.commit_group;" ::: "memory")
#define CPWAIT2()      asm volatile("cp.async.wait_group 2;" ::: "memory")

#define LDSM4(r0,r1,r2,r3,addr) \
    asm volatile("ldmatrix.sync.aligned.m8n8.x4.shared.b16 {%0,%1,%2,%3}, [%4];" \
        : "=r"(r0),"=r"(r1),"=r"(r2),"=r"(r3) : "r"(addr))

#define MMA16816(d,a,b0,b1) \
    asm volatile("mma.sync.aligned.m16n8k16.row.col.f32.bf16.bf16.f32 " \
        "{%0,%1,%2,%3}, {%4,%5,%6,%7}, {%8,%9}, {%0,%1,%2,%3};" \
        : "+f"((d)[0]),"+f"((d)[1]),"+f"((d)[2]),"+f"((d)[3]) \
        : "r"((a)[0]),"r"((a)[1]),"r"((a)[2]),"r"((a)[3]), "r"(b0),"r"(b1))

__device__ __forceinline__ uint32_t pk_hi(float a, float b) {
    return (uint32_t)__bfloat16_as_ushort(__float2bfloat16(a))
         | ((uint32_t)__bfloat16_as_ushort(__float2bfloat16(b)) << 16);
}
__device__ __forceinline__ float bf_res(float v) {   // v - bf16(v)
    return v - __bfloat162float(__float2bfloat16(v));
}

// ---------------- phase 1: CSR build + gather reductions ---------------------
__global__ void zero_counts() {
    int i = blockIdx.x * blockDim.x + threadIdx.x;
    if (i < N_NODES) g_cnt[i] = 0;
}
__global__ void count_kernel(const int* __restrict__ dst) {
    int i = blockIdx.x * blockDim.x + threadIdx.x;
    if (i < N_EDGES) atomicAdd(&g_cnt[dst[i]], 1);
}
__global__ void scan_kernel() {            // single block, 1024 threads
    __shared__ int sh[1024];
    __shared__ int carry;
    int tid = threadIdx.x;
    if (tid == 0) carry = 0;
    __syncthreads();
    for (int base = 0; base < N_NODES; base += 1024) {
        int i = base + tid;
        int v = (i < N_NODES) ? g_cnt[i] : 0;
        sh[tid] = v;
        __syncthreads();
        for (int off = 1; off < 1024; off <<= 1) {
            int t = (tid >= off) ? sh[tid - off] : 0;
            __syncthreads();
            sh[tid] += t;
            __syncthreads();
        }
        if (i < N_NODES) {
            g_start[i] = carry + sh[tid] - v;   // exclusive
            g_cnt[i] = 0;                       // reset: becomes fill cursor
        }
        __syncthreads();
        if (tid == 1023) carry += sh[1023];
        __syncthreads();
    }
    if (tid == 0) g_start[N_NODES] = N_EDGES;   // sentinel
}
__global__ void fill_kernel(const int* __restrict__ dst) {
    int i = blockIdx.x * blockDim.x + threadIdx.x;
    if (i >= N_EDGES) return;
    int c = dst[i];
    int p = atomicAdd(&g_cnt[c], 1);
    g_eidx[g_start[c] + p] = i;
}
// warp per node: lanes own feature cols {l, l+32, l+64}
__global__ void gather_kernel(const float* __restrict__ ea) {
    int w = (blockIdx.x * blockDim.x + threadIdx.x) >> 5;
    int lid = threadIdx.x & 31;
    if (w >= N_NODES) return;
    int s = g_start[w], d = g_start[w + 1] - s;
    float ninf = __int_as_float(0xff800000);
    float s0 = 0.f, s1 = 0.f, s2 = 0.f;
    float m0 = ninf, m1 = ninf, m2 = ninf;
    int e = (d > 0) ? g_eidx[s] : 0;
    for (int j = 0; j < d; ++j) {
        int en = (j + 1 < d) ? g_eidx[s + j + 1] : 0;
        const float* r = ea + (size_t)e * EDGE_F;
        float v0 = r[lid], v1 = r[lid + 32], v2 = r[lid + 64];
        s0 += v0; s1 += v1; s2 += v2;
        m0 = fmaxf(m0, v0); m1 = fmaxf(m1, v1); m2 = fmaxf(m2, v2);
        e = en;
    }
    float* o = g_agg + (size_t)w * 192;
    o[lid]       = s0; o[lid + 32]      = s1; o[lid + 64]      = s2;
    o[96 + lid]  = m0; o[96 + lid + 32] = m1; o[96 + lid + 64] = m2;
}

// compose 608-col MLP input, bf16-split into g_Ah/g_Al, pad to 640/MPAD
__global__ void convert_kernel(const float* __restrict__ x, const float* __restrict__ u,
                               const int* __restrict__ batch) {
    int i = blockIdx.x * blockDim.x + threadIdx.x;      // MPAD*160 tasks (4 cols each)
    if (i >= MPAD * 160) return;
    int n = i / 160, q = i - n * 160;
    float v[4] = {0.f, 0.f, 0.f, 0.f};
    if (n < N_NODES) {
        int cnt = g_start[n + 1] - g_start[n];
        float inv = cnt > 0 ? 1.f / (float)cnt : 0.f;
#pragma unroll
        for (int t = 0; t < 4; ++t) {
            int c = q * 4 + t;
            float w;
            if (c < 256)      w = x[(size_t)n * NODE_F + c];
            else if (c < 352) w = g_agg[(size_t)n * 192 + (c - 256)];
            else if (c < 448) w = cnt > 0 ? g_agg[(size_t)n * 192 + 96 + (c - 352)] : 0.f;
            else if (c < 544) w = g_agg[(size_t)n * 192 + (c - 448)] * inv;
            else if (c < 608) w = u[(size_t)batch[n] * GLOB_F + (c - 544)];
            else              w = 0.f;
            v[t] = w;
        }
    }
    size_t off = (size_t)n * K1PAD + 4 * q;
    *(uint2*)(g_Ah + off) = make_uint2(pk_hi(v[0], v[1]), pk_hi(v[2], v[3]));
    *(uint2*)(g_Al + off) = make_uint2(pk_hi(bf_res(v[0]), bf_res(v[1])),
                                       pk_hi(bf_res(v[2]), bf_res(v[3])));
}

// transpose + split weights: B1[n][k] = W1[k][n], B2[n][k] = W2[k][n]
__global__ void prep_w(const float* __restrict__ W1, const float* __restrict__ W2) {
    int i = blockIdx.x * blockDim.x + threadIdx.x;
    const int T1 = HIDDEN * 160;
    if (i < T1) {
        int n = i / 160, q = i - n * 160;
        float v[4];
#pragma unroll
        for (int t = 0; t < 4; ++t) {
            int k = 4 * q + t;
            v[t] = (k < 608) ? W1[(size_t)k * HIDDEN + n] : 0.f;
        }
        size_t off = (size_t)n * K1PAD + 4 * q;
        *(uint2*)(g_B1h + off) = make_uint2(pk_hi(v[0], v[1]), pk_hi(v[2], v[3]));
        *(uint2*)(g_B1l + off) = make_uint2(pk_hi(bf_res(v[0]), bf_res(v[1])),
                                            pk_hi(bf_res(v[2]), bf_res(v[3])));
    } else {
        int j = i - T1;
        if (j >= NODE_F * 256) return;
        int n = j / 256, q = j - n * 256;
        float v[4];
#pragma unroll
        for (int t = 0; t < 4; ++t) v[t] = W2[(size_t)(4 * q + t) * NODE_F + n];
        size_t off = (size_t)n * HIDDEN + 4 * q;
        *(uint2*)(g_B2h + off) = make_uint2(pk_hi(v[0], v[1]), pk_hi(v[2], v[3]));
        *(uint2*)(g_B2l + off) = make_uint2(pk_hi(bf_res(v[0]), bf_res(v[1])),
                                            pk_hi(bf_res(v[2]), bf_res(v[3])));
    }
}

// ---------------- phase 2: warp-mma bf16 3-term GEMM -------------------------
// CTA tile 128x128, BK=32. 8 warps 4(m) x 2(n); warp tile 32x64.
// SMEM stage: Ah Al Bh Bl 8KB each = 32KB; 3 stages = 96KB.
#define STAGE_B 32768

__device__ __forceinline__ void issue_stage(
    uint32_t smemS, const __nv_bfloat16* __restrict__ Ah, const __nv_bfloat16* __restrict__ Al,
    const __nv_bfloat16* __restrict__ Bh, const __nv_bfloat16* __restrict__ Bl,
    int mBase, int cBase, int Kpad, int k0, int tid)
{
#pragma unroll
    for (int j = 0; j < 8; ++j) {
        int t8  = tid + 256 * j;
        int tile = t8 >> 9;
        int idx  = t8 & 511;
        int row  = idx >> 2;
        int ch   = idx & 3;
        uint32_t dst = smemS + tile * 8192 + row * 64 + ((ch ^ (row & 3)) << 4);
        const __nv_bfloat16* src;
        if (tile == 0)      src = Ah + (size_t)(mBase + row) * Kpad + k0 + ch * 8;
        else if (tile == 1) src = Al + (size_t)(mBase + row) * Kpad + k0 + ch * 8;
        else if (tile == 2) src = Bh + (size_t)(cBase + row) * Kpad + k0 + ch * 8;
        else                src = Bl + (size_t)(cBase + row) * Kpad + k0 + ch * 8;
        CPASYNC16(dst, src);
    }
}

template<int EPI>
__global__ __launch_bounds__(256, 2)
void mma_gemm(const __nv_bfloat16* __restrict__ Ah, const __nv_bfloat16* __restrict__ Al,
              const __nv_bfloat16* __restrict__ Bh, const __nv_bfloat16* __restrict__ Bl,
              const float* __restrict__ bias, const float* __restrict__ resid,
              __nv_bfloat16* __restrict__ Oh, __nv_bfloat16* __restrict__ Ol,
              float* __restrict__ outF, int Kpad, int ldo)
{
    extern __shared__ char smem[];
    const uint32_t sb = smem_u32(smem);
    const int tid = threadIdx.x;
    const int wid = tid >> 5, lid = tid & 31;
    const int wm = wid >> 1, wn = wid & 1;          // 4x2 warp grid

    const int mBase = blockIdx.y * 128;
    const int cBase = blockIdx.x * 128;
    const int NC = Kpad >> 5;

    const int aRow = wm * 32 + ((lid >> 3) & 1) * 8 + (lid & 7);
    const int aK   = (lid >> 4) & 1;
    const int aB   = aRow * 64, aM = aRow & 3;
    const int bRow = wn * 64 + ((lid >> 4) & 1) * 8 + (lid & 7);
    const int bK   = (lid >> 3) & 1;
    const int bB   = bRow * 64, bM = bRow & 3;

    float acc[2][8][4];
#pragma unroll
    for (int m = 0; m < 2; ++m)
#pragma unroll
        for (int n = 0; n < 8; ++n)
#pragma unroll
            for (int c = 0; c < 4; ++c) acc[m][n][c] = 0.f;

    issue_stage(sb,           Ah, Al, Bh, Bl, mBase, cBase, Kpad, 0,  tid); CPCOMMIT();
    issue_stage(sb + STAGE_B, Ah, Al, Bh, Bl, mBase, cBase, Kpad, 32, tid); CPCOMMIT();

    for (int i = 0; i < NC; ++i) {
        if (i + 2 < NC)
            issue_stage(sb + ((i + 2) % 3) * STAGE_B, Ah, Al, Bh, Bl,
                        mBase, cBase, Kpad, (i + 2) * 32, tid);
        CPCOMMIT();
        CPWAIT2();
        __syncthreads();

        const uint32_t S = sb + (i % 3) * STAGE_B;
#pragma unroll
        for (int ks = 0; ks < 2; ++ks) {
            uint32_t ah[2][4], al[2][4], bh[4][4], bl[4][4];
            const int kcA = ks * 2 + aK;
            const uint32_t offA = ((kcA ^ aM) << 4) + aB;
#pragma unroll
            for (int ms = 0; ms < 2; ++ms) {
                LDSM4(ah[ms][0], ah[ms][1], ah[ms][2], ah[ms][3], S + offA + ms * 1024);
                LDSM4(al[ms][0], al[ms][1], al[ms][2], al[ms][3], S + 8192 + offA + ms * 1024);
            }
            const int kcB = ks * 2 + bK;
            const uint32_t offB = ((kcB ^ bM) << 4) + bB;
#pragma unroll
            for (int nb = 0; nb < 4; ++nb) {
                LDSM4(bh[nb][0], bh[nb][1], bh[nb][2], bh[nb][3], S + 16384 + offB + nb * 1024);
                LDSM4(bl[nb][0], bl[nb][1], bl[nb][2], bl[nb][3], S + 24576 + offB + nb * 1024);
            }
#pragma unroll
            for (int ms = 0; ms < 2; ++ms)
#pragma unroll
                for (int ns = 0; ns < 8; ++ns) {
                    const int nb = ns >> 1, h = (ns & 1) * 2;
                    MMA16816(acc[ms][ns], ah[ms], bh[nb][h], bh[nb][h + 1]);
                    MMA16816(acc[ms][ns], ah[ms], bl[nb][h], bl[nb][h + 1]);
                    MMA16816(acc[ms][ns], al[ms], bh[nb][h], bh[nb][h + 1]);
                }
        }
        __syncthreads();
    }

    // ---------------- epilogue ----------------
    const int l4 = lid >> 2, l2 = (lid & 3) * 2;
#pragma unroll
    for (int ms = 0; ms < 2; ++ms) {
        const int r0 = mBase + wm * 32 + ms * 16 + l4;
        const int r1 = r0 + 8;
#pragma unroll
        for (int ns = 0; ns < 8; ++ns) {
            const int col = cBase + wn * 64 + ns * 8 + l2;
            const float b0 = __ldg(&bias[col]), b1 = __ldg(&bias[col + 1]);
            float v00 = acc[ms][ns][0] + b0, v01 = acc[ms][ns][1] + b1;
            float v10 = acc[ms][ns][2] + b0, v11 = acc[ms][ns][3] + b1;
            if (EPI == 1) {
                v00 = fmaxf(v00, 0.f); v01 = fmaxf(v01, 0.f);
                v10 = fmaxf(v10, 0.f); v11 = fmaxf(v11, 0.f);
                *(uint32_t*)(Oh + (size_t)r0 * ldo + col) = pk_hi(v00, v01);
                *(uint32_t*)(Ol + (size_t)r0 * ldo + col) = pk_hi(bf_res(v00), bf_res(v01));
                *(uint32_t*)(Oh + (size_t)r1 * ldo + col) = pk_hi(v10, v11);
                *(uint32_t*)(Ol + (size_t)r1 * ldo + col) = pk_hi(bf_res(v10), bf_res(v11));
            } else {
                if (r0 < N_NODES) {
                    const float* xr = resid + (size_t)r0 * NODE_F + col;
                    *(float2*)(outF + (size_t)r0 * ldo + col) =
                        make_float2(v00 + xr[0], v01 + xr[1]);
                }
                if (r1 < N_NODES) {
                    const float* xr = resid + (size_t)r1 * NODE_F + col;
                    *(float2*)(outF + (size_t)r1 * ldo + col) =
                        make_float2(v10 + xr[1 - 1] + 0.f, v11 + xr[1]);
                }
            }
        }
    }
}

// ---------------------------------------------------------------------------
extern "C" void kernel_launch(void* const* d_in, const int* in_sizes, int n_in,
                              void* d_out, int out_size) {
    const float* x     = (const float*)d_in[0];
    const float* ea    = (const float*)d_in[1];
    const float* u     = (const float*)d_in[2];
    const float* W1    = (const float*)d_in[3];
    const float* b1    = (const float*)d_in[4];
    const float* W2    = (const float*)d_in[5];
    const float* b2    = (const float*)d_in[6];
    const int*   ei    = (const int*)  d_in[7];   // [2, N_EDGES]; row 1 = dst
    const int*   batch = (const int*)  d_in[8];
    float*       out   = (float*)d_out;
    const int*   dst   = ei + N_EDGES;

    __nv_bfloat16 *Ah, *Al, *Hh, *Hl, *B1h, *B1l, *B2h, *B2l;
    cudaGetSymbolAddress((void**)&Ah,  g_Ah);
    cudaGetSymbolAddress((void**)&Al,  g_Al);
    cudaGetSymbolAddress((void**)&Hh,  g_Hh);
    cudaGetSymbolAddress((void**)&Hl,  g_Hl);
    cudaGetSymbolAddress((void**)&B1h, g_B1h);
    cudaGetSymbolAddress((void**)&B1l, g_B1l);
    cudaGetSymbolAddress((void**)&B2h, g_B2h);
    cudaGetSymbolAddress((void**)&B2l, g_B2l);

    const int SMEM_SZ = 3 * STAGE_B;
    cudaFuncSetAttribute(mma_gemm<1>, cudaFuncAttributeMaxDynamicSharedMemorySize, SMEM_SZ);
    cudaFuncSetAttribute(mma_gemm<2>, cudaFuncAttributeMaxDynamicSharedMemorySize, SMEM_SZ);

    // CSR build + gather reductions
    zero_counts<<<(N_NODES + 255) / 256, 256>>>();
    count_kernel<<<(N_EDGES + 255) / 256, 256>>>(dst);
    scan_kernel<<<1, 1024>>>();
    fill_kernel<<<(N_EDGES + 255) / 256, 256>>>(dst);
    gather_kernel<<<(N_NODES * 32 + 255) / 256, 256>>>(ea);

    prep_w<<<(HIDDEN * 160 + NODE_F * 256 + 255) / 256, 256>>>(W1, W2);
    convert_kernel<<<(MPAD * 160 + 255) / 256, 256>>>(x, u, batch);

    mma_gemm<1><<<dim3(HIDDEN / 128, MTILES), 256, SMEM_SZ>>>(
        Ah, Al, B1h, B1l, b1, nullptr, Hh, Hl, nullptr, K1PAD, HIDDEN);
    mma_gemm<2><<<dim3(NODE_F / 128, MTILES), 256, SMEM_SZ>>>(
        Hh, Hl, B2h, B2l, b2, x, nullptr, nullptr, out, HIDDEN, NODE_F);
}

// round 8
// speedup vs baseline: 2.5275x; 1.0494x over previous
#include <cuda_runtime.h>
#include <cuda_bf16.h>
#include <cstdint>

#define N_NODES 50000
#define N_EDGES 800000
#define EDGE_F  96
#define NODE_F  256
#define GLOB_F  64
#define HIDDEN  1024
#define N_GRAPHS 8
#define K1PAD   576              // 544 real cols (x|sum|max|mean) padded to /32
#define MTILES  391
#define MPAD    (MTILES*128)     // 50048

// ---------------- device scratch (allocation-free per harness rules) -------
__device__ float g_agg[(size_t)N_NODES*192];       // sum[0:96), max[96:192)
__device__ int   g_cnt[N_NODES];                   // counts, then fill-cursor
__device__ int   g_start[N_NODES + 1];             // CSR offsets (+sentinel)
__device__ int   g_eidx[N_EDGES];
__device__ float g_ub[N_GRAPHS * HIDDEN];          // b1 + u[g] @ W1u
__device__ __nv_bfloat16 g_Ah[(size_t)MPAD*K1PAD];
__device__ __nv_bfloat16 g_Al[(size_t)MPAD*K1PAD];
__device__ __nv_bfloat16 g_Hh[(size_t)MPAD*HIDDEN];
__device__ __nv_bfloat16 g_Hl[(size_t)MPAD*HIDDEN];
__device__ __nv_bfloat16 g_B1h[(size_t)HIDDEN*K1PAD];
__device__ __nv_bfloat16 g_B1l[(size_t)HIDDEN*K1PAD];
__device__ __nv_bfloat16 g_B2h[(size_t)NODE_F*HIDDEN];
__device__ __nv_bfloat16 g_B2l[(size_t)NODE_F*HIDDEN];

// ---------------- PTX helpers ----------------------------------------------
__device__ __forceinline__ uint32_t smem_u32(const void* p) {
    uint32_t a;
    asm("{ .reg .u64 t; cvta.to.shared.u64 t, %1; cvt.u32.u64 %0, t; }" : "=r"(a) : "l"(p));
    return a;
}
#define CPASYNC16(s,g) asm volatile("cp.async.cg.shared.global [%0], [%1], 16;" :: "r"(s), "l"(g))
#define CPCOMMIT()     asm volatile("cp.async.commit_group;" ::: "memory")
#define CPWAIT2()      asm volatile("cp.async.wait_group 2;" ::: "memory")

#define LDSM4(r0,r1,r2,r3,addr) \
    asm volatile("ldmatrix.sync.aligned.m8n8.x4.shared.b16 {%0,%1,%2,%3}, [%4];" \
        : "=r"(r0),"=r"(r1),"=r"(r2),"=r"(r3) : "r"(addr))

#define MMA16816(d,a,b0,b1) \
    asm volatile("mma.sync.aligned.m16n8k16.row.col.f32.bf16.bf16.f32 " \
        "{%0,%1,%2,%3}, {%4,%5,%6,%7}, {%8,%9}, {%0,%1,%2,%3};" \
        : "+f"((d)[0]),"+f"((d)[1]),"+f"((d)[2]),"+f"((d)[3]) \
        : "r"((a)[0]),"r"((a)[1]),"r"((a)[2]),"r"((a)[3]), "r"(b0),"r"(b1))

__device__ __forceinline__ uint32_t pk_hi(float a, float b) {
    return (uint32_t)__bfloat16_as_ushort(__float2bfloat16(a))
         | ((uint32_t)__bfloat16_as_ushort(__float2bfloat16(b)) << 16);
}
__device__ __forceinline__ float bf_res(float v) {   // v - bf16(v)
    return v - __bfloat162float(__float2bfloat16(v));
}

// ---------------- phase 1: CSR build + gather reductions ---------------------
__global__ void zero_counts() {
    int i = blockIdx.x * blockDim.x + threadIdx.x;
    if (i < N_NODES) g_cnt[i] = 0;
}
__global__ void count_kernel(const int* __restrict__ dst) {
    int i = blockIdx.x * blockDim.x + threadIdx.x;
    if (i < N_EDGES) atomicAdd(&g_cnt[dst[i]], 1);
}
__global__ void scan_kernel() {            // single block, 1024 threads
    __shared__ int sh[1024];
    __shared__ int carry;
    int tid = threadIdx.x;
    if (tid == 0) carry = 0;
    __syncthreads();
    for (int base = 0; base < N_NODES; base += 1024) {
        int i = base + tid;
        int v = (i < N_NODES) ? g_cnt[i] : 0;
        sh[tid] = v;
        __syncthreads();
        for (int off = 1; off < 1024; off <<= 1) {
            int t = (tid >= off) ? sh[tid - off] : 0;
            __syncthreads();
            sh[tid] += t;
            __syncthreads();
        }
        if (i < N_NODES) {
            g_start[i] = carry + sh[tid] - v;   // exclusive
            g_cnt[i] = 0;                       // reset: becomes fill cursor
        }
        __syncthreads();
        if (tid == 1023) carry += sh[1023];
        __syncthreads();
    }
    if (tid == 0) g_start[N_NODES] = N_EDGES;   // sentinel
}
__global__ void fill_kernel(const int* __restrict__ dst) {
    int i = blockIdx.x * blockDim.x + threadIdx.x;
    if (i >= N_EDGES) return;
    int c = dst[i];
    int p = atomicAdd(&g_cnt[c], 1);
    g_eidx[g_start[c] + p] = i;
}
// warp per node, unrolled x4: 12 independent row-loads in flight per warp.
__global__ void gather_kernel(const float* __restrict__ ea) {
    int w = (blockIdx.x * blockDim.x + threadIdx.x) >> 5;
    int lid = threadIdx.x & 31;
    if (w >= N_NODES) return;
    int s = g_start[w], d = g_start[w + 1] - s;
    float ninf = __int_as_float(0xff800000);
    float s0 = 0.f, s1 = 0.f, s2 = 0.f;
    float m0 = ninf, m1 = ninf, m2 = ninf;
    int j = 0;
    for (; j + 4 <= d; j += 4) {
        int e0 = g_eidx[s + j],     e1 = g_eidx[s + j + 1];
        int e2 = g_eidx[s + j + 2], e3 = g_eidx[s + j + 3];
        const float* r0 = ea + (size_t)e0 * EDGE_F;
        const float* r1 = ea + (size_t)e1 * EDGE_F;
        const float* r2 = ea + (size_t)e2 * EDGE_F;
        const float* r3 = ea + (size_t)e3 * EDGE_F;
        float a0 = r0[lid], a1 = r0[lid + 32], a2 = r0[lid + 64];
        float b0 = r1[lid], b1 = r1[lid + 32], b2 = r1[lid + 64];
        float c0 = r2[lid], c1 = r2[lid + 32], c2 = r2[lid + 64];
        float d0 = r3[lid], d1 = r3[lid + 32], d2 = r3[lid + 64];
        s0 += a0 + b0 + c0 + d0;
        s1 += a1 + b1 + c1 + d1;
        s2 += a2 + b2 + c2 + d2;
        m0 = fmaxf(fmaxf(fmaxf(m0, a0), fmaxf(b0, c0)), d0);
        m1 = fmaxf(fmaxf(fmaxf(m1, a1), fmaxf(b1, c1)), d1);
        m2 = fmaxf(fmaxf(fmaxf(m2, a2), fmaxf(b2, c2)), d2);
    }
    for (; j < d; ++j) {
        int e = g_eidx[s + j];
        const float* r = ea + (size_t)e * EDGE_F;
        float v0 = r[lid], v1 = r[lid + 32], v2 = r[lid + 64];
        s0 += v0; s1 += v1; s2 += v2;
        m0 = fmaxf(m0, v0); m1 = fmaxf(m1, v1); m2 = fmaxf(m2, v2);
    }
    float* o = g_agg + (size_t)w * 192;
    o[lid]       = s0; o[lid + 32]      = s1; o[lid + 64]      = s2;
    o[96 + lid]  = m0; o[96 + lid + 32] = m1; o[96 + lid + 64] = m2;
}

// u-bias table: ub[g][n] = b1[n] + sum_k u[g][k] * W1[544+k][n]
__global__ void ub_kernel(const float* __restrict__ u, const float* __restrict__ W1,
                          const float* __restrict__ b1) {
    int i = blockIdx.x * blockDim.x + threadIdx.x;   // N_GRAPHS*HIDDEN
    if (i >= N_GRAPHS * HIDDEN) return;
    int g = i / HIDDEN, n = i - g * HIDDEN;
    float acc = b1[n];
#pragma unroll 8
    for (int k = 0; k < GLOB_F; ++k)
        acc += u[(size_t)g * GLOB_F + k] * W1[(size_t)(544 + k) * HIDDEN + n];
    g_ub[i] = acc;
}

// compose 544-col MLP input (x|sum|max|mean), bf16-split, pad to 576/MPAD
__global__ void convert_kernel(const float* __restrict__ x) {
    int i = blockIdx.x * blockDim.x + threadIdx.x;      // MPAD*144 tasks (4 cols each)
    if (i >= MPAD * 144) return;
    int n = i / 144, q = i - n * 144;
    float v[4] = {0.f, 0.f, 0.f, 0.f};
    if (n < N_NODES) {
        int cnt = g_start[n + 1] - g_start[n];
        float inv = cnt > 0 ? 1.f / (float)cnt : 0.f;
#pragma unroll
        for (int t = 0; t < 4; ++t) {
            int c = q * 4 + t;
            float w;
            if (c < 256)      w = x[(size_t)n * NODE_F + c];
            else if (c < 352) w = g_agg[(size_t)n * 192 + (c - 256)];
            else if (c < 448) w = cnt > 0 ? g_agg[(size_t)n * 192 + 96 + (c - 352)] : 0.f;
            else if (c < 544) w = g_agg[(size_t)n * 192 + (c - 448)] * inv;
            else              w = 0.f;
            v[t] = w;
        }
    }
    size_t off = (size_t)n * K1PAD + 4 * q;
    *(uint2*)(g_Ah + off) = make_uint2(pk_hi(v[0], v[1]), pk_hi(v[2], v[3]));
    *(uint2*)(g_Al + off) = make_uint2(pk_hi(bf_res(v[0]), bf_res(v[1])),
                                       pk_hi(bf_res(v[2]), bf_res(v[3])));
}

// transpose + split weights: B1[n][k] = W1[k][n] (k<544), B2[n][k] = W2[k][n]
__global__ void prep_w(const float* __restrict__ W1, const float* __restrict__ W2) {
    int i = blockIdx.x * blockDim.x + threadIdx.x;
    const int T1 = HIDDEN * 144;
    if (i < T1) {
        int n = i / 144, q = i - n * 144;
        float v[4];
#pragma unroll
        for (int t = 0; t < 4; ++t) {
            int k = 4 * q + t;
            v[t] = (k < 544) ? W1[(size_t)k * HIDDEN + n] : 0.f;
        }
        size_t off = (size_t)n * K1PAD + 4 * q;
        *(uint2*)(g_B1h + off) = make_uint2(pk_hi(v[0], v[1]), pk_hi(v[2], v[3]));
        *(uint2*)(g_B1l + off) = make_uint2(pk_hi(bf_res(v[0]), bf_res(v[1])),
                                            pk_hi(bf_res(v[2]), bf_res(v[3])));
    } else {
        int j = i - T1;
        if (j >= NODE_F * 256) return;
        int n = j / 256, q = j - n * 256;
        float v[4];
#pragma unroll
        for (int t = 0; t < 4; ++t) v[t] = W2[(size_t)(4 * q + t) * NODE_F + n];
        size_t off = (size_t)n * HIDDEN + 4 * q;
        *(uint2*)(g_B2h + off) = make_uint2(pk_hi(v[0], v[1]), pk_hi(v[2], v[3]));
        *(uint2*)(g_B2l + off) = make_uint2(pk_hi(bf_res(v[0]), bf_res(v[1])),
                                            pk_hi(bf_res(v[2]), bf_res(v[3])));
    }
}

// ---------------- phase 2: warp-mma bf16 3-term GEMM -------------------------
// CTA tile 128x128, BK=32. 8 warps 4(m) x 2(n); warp tile 32x64.
// SMEM stage: Ah Al Bh Bl 8KB each = 32KB; 3 stages = 96KB.
#define STAGE_B 32768

__device__ __forceinline__ void issue_stage(
    uint32_t smemS, const __nv_bfloat16* __restrict__ Ah, const __nv_bfloat16* __restrict__ Al,
    const __nv_bfloat16* __restrict__ Bh, const __nv_bfloat16* __restrict__ Bl,
    int mBase, int cBase, int Kpad, int k0, int tid)
{
#pragma unroll
    for (int j = 0; j < 8; ++j) {
        int t8  = tid + 256 * j;
        int tile = t8 >> 9;
        int idx  = t8 & 511;
        int row  = idx >> 2;
        int ch   = idx & 3;
        uint32_t dst = smemS + tile * 8192 + row * 64 + ((ch ^ (row & 3)) << 4);
        const __nv_bfloat16* src;
        if (tile == 0)      src = Ah + (size_t)(mBase + row) * Kpad + k0 + ch * 8;
        else if (tile == 1) src = Al + (size_t)(mBase + row) * Kpad + k0 + ch * 8;
        else if (tile == 2) src = Bh + (size_t)(cBase + row) * Kpad + k0 + ch * 8;
        else                src = Bl + (size_t)(cBase + row) * Kpad + k0 + ch * 8;
        CPASYNC16(dst, src);
    }
}

template<int EPI>
__global__ __launch_bounds__(256, 2)
void mma_gemm(const __nv_bfloat16* __restrict__ Ah, const __nv_bfloat16* __restrict__ Al,
              const __nv_bfloat16* __restrict__ Bh, const __nv_bfloat16* __restrict__ Bl,
              const float* __restrict__ bias, const float* __restrict__ resid,
              const int* __restrict__ batchArr, const float* __restrict__ ubT,
              __nv_bfloat16* __restrict__ Oh, __nv_bfloat16* __restrict__ Ol,
              float* __restrict__ outF, int Kpad, int ldo)
{
    extern __shared__ char smem[];
    const uint32_t sb = smem_u32(smem);
    const int tid = threadIdx.x;
    const int wid = tid >> 5, lid = tid & 31;
    const int wm = wid >> 1, wn = wid & 1;          // 4x2 warp grid

    const int mBase = blockIdx.y * 128;
    const int cBase = blockIdx.x * 128;
    const int NC = Kpad >> 5;

    const int aRow = wm * 32 + ((lid >> 3) & 1) * 8 + (lid & 7);
    const int aK   = (lid >> 4) & 1;
    const int aB   = aRow * 64, aM = aRow & 3;
    const int bRow = wn * 64 + ((lid >> 4) & 1) * 8 + (lid & 7);
    const int bK   = (lid >> 3) & 1;
    const int bB   = bRow * 64, bM = bRow & 3;

    float acc[2][8][4];
#pragma unroll
    for (int m = 0; m < 2; ++m)
#pragma unroll
        for (int n = 0; n < 8; ++n)
#pragma unroll
            for (int c = 0; c < 4; ++c) acc[m][n][c] = 0.f;

    issue_stage(sb,           Ah, Al, Bh, Bl, mBase, cBase, Kpad, 0,  tid); CPCOMMIT();
    issue_stage(sb + STAGE_B, Ah, Al, Bh, Bl, mBase, cBase, Kpad, 32, tid); CPCOMMIT();

    for (int i = 0; i < NC; ++i) {
        if (i + 2 < NC)
            issue_stage(sb + ((i + 2) % 3) * STAGE_B, Ah, Al, Bh, Bl,
                        mBase, cBase, Kpad, (i + 2) * 32, tid);
        CPCOMMIT();
        CPWAIT2();
        __syncthreads();

        const uint32_t S = sb + (i % 3) * STAGE_B;
#pragma unroll
        for (int ks = 0; ks < 2; ++ks) {
            uint32_t ah[2][4], al[2][4], bh[4][4], bl[4][4];
            const int kcA = ks * 2 + aK;
            const uint32_t offA = ((kcA ^ aM) << 4) + aB;
#pragma unroll
            for (int ms = 0; ms < 2; ++ms) {
                LDSM4(ah[ms][0], ah[ms][1], ah[ms][2], ah[ms][3], S + offA + ms * 1024);
                LDSM4(al[ms][0], al[ms][1], al[ms][2], al[ms][3], S + 8192 + offA + ms * 1024);
            }
            const int kcB = ks * 2 + bK;
            const uint32_t offB = ((kcB ^ bM) << 4) + bB;
#pragma unroll
            for (int nb = 0; nb < 4; ++nb) {
                LDSM4(bh[nb][0], bh[nb][1], bh[nb][2], bh[nb][3], S + 16384 + offB + nb * 1024);
                LDSM4(bl[nb][0], bl[nb][1], bl[nb][2], bl[nb][3], S + 24576 + offB + nb * 1024);
            }
#pragma unroll
            for (int ms = 0; ms < 2; ++ms)
#pragma unroll
                for (int ns = 0; ns < 8; ++ns) {
                    const int nb = ns >> 1, h = (ns & 1) * 2;
                    MMA16816(acc[ms][ns], ah[ms], bh[nb][h], bh[nb][h + 1]);
                    MMA16816(acc[ms][ns], ah[ms], bl[nb][h], bl[nb][h + 1]);
                    MMA16816(acc[ms][ns], al[ms], bh[nb][h], bh[nb][h + 1]);
                }
        }
        __syncthreads();
    }

    // ---------------- epilogue ----------------
    const int l4 = lid >> 2, l2 = (lid & 3) * 2;
#pragma unroll
    for (int ms = 0; ms < 2; ++ms) {
        const int r0 = mBase + wm * 32 + ms * 16 + l4;
        const int r1 = r0 + 8;
        const float* ub0 = nullptr;
        const float* ub1 = nullptr;
        if (EPI == 1) {
            int g0 = (r0 < N_NODES) ? __ldg(&batchArr[r0]) : 0;
            int g1 = (r1 < N_NODES) ? __ldg(&batchArr[r1]) : 0;
            ub0 = ubT + (size_t)g0 * HIDDEN;
            ub1 = ubT + (size_t)g1 * HIDDEN;
        }
#pragma unroll
        for (int ns = 0; ns < 8; ++ns) {
            const int col = cBase + wn * 64 + ns * 8 + l2;
            if (EPI == 1) {
                float v00 = fmaxf(acc[ms][ns][0] + __ldg(&ub0[col]),     0.f);
                float v01 = fmaxf(acc[ms][ns][1] + __ldg(&ub0[col + 1]), 0.f);
                float v10 = fmaxf(acc[ms][ns][2] + __ldg(&ub1[col]),     0.f);
                float v11 = fmaxf(acc[ms][ns][3] + __ldg(&ub1[col + 1]), 0.f);
                *(uint32_t*)(Oh + (size_t)r0 * ldo + col) = pk_hi(v00, v01);
                *(uint32_t*)(Ol + (size_t)r0 * ldo + col) = pk_hi(bf_res(v00), bf_res(v01));
                *(uint32_t*)(Oh + (size_t)r1 * ldo + col) = pk_hi(v10, v11);
                *(uint32_t*)(Ol + (size_t)r1 * ldo + col) = pk_hi(bf_res(v10), bf_res(v11));
            } else {
                const float b0 = __ldg(&bias[col]), b1v = __ldg(&bias[col + 1]);
                if (r0 < N_NODES) {
                    const float* xr = resid + (size_t)r0 * NODE_F + col;
                    *(float2*)(outF + (size_t)r0 * ldo + col) =
                        make_float2(acc[ms][ns][0] + b0 + xr[0],
                                    acc[ms][ns][1] + b1v + xr[1]);
                }
                if (r1 < N_NODES) {
                    const float* xr = resid + (size_t)r1 * NODE_F + col;
                    *(float2*)(outF + (size_t)r1 * ldo + col) =
                        make_float2(acc[ms][ns][2] + b0 + xr[0],
                                    acc[ms][ns][3] + b1v + xr[1]);
                }
            }
        }
    }
}

// ---------------------------------------------------------------------------
extern "C" void kernel_launch(void* const* d_in, const int* in_sizes, int n_in,
                              void* d_out, int out_size) {
    const float* x     = (const float*)d_in[0];
    const float* ea    = (const float*)d_in[1];
    const float* u     = (const float*)d_in[2];
    const float* W1    = (const float*)d_in[3];
    const float* b1    = (const float*)d_in[4];
    const float* W2    = (const float*)d_in[5];
    const float* b2    = (const float*)d_in[6];
    const int*   ei    = (const int*)  d_in[7];   // [2, N_EDGES]; row 1 = dst
    const int*   batch = (const int*)  d_in[8];
    float*       out   = (float*)d_out;
    const int*   dst   = ei + N_EDGES;

    __nv_bfloat16 *Ah, *Al, *Hh, *Hl, *B1h, *B1l, *B2h, *B2l;
    float* ubT;
    cudaGetSymbolAddress((void**)&Ah,  g_Ah);
    cudaGetSymbolAddress((void**)&Al,  g_Al);
    cudaGetSymbolAddress((void**)&Hh,  g_Hh);
    cudaGetSymbolAddress((void**)&Hl,  g_Hl);
    cudaGetSymbolAddress((void**)&B1h, g_B1h);
    cudaGetSymbolAddress((void**)&B1l, g_B1l);
    cudaGetSymbolAddress((void**)&B2h, g_B2h);
    cudaGetSymbolAddress((void**)&B2l, g_B2l);
    cudaGetSymbolAddress((void**)&ubT, g_ub);

    const int SMEM_SZ = 3 * STAGE_B;
    cudaFuncSetAttribute(mma_gemm<1>, cudaFuncAttributeMaxDynamicSharedMemorySize, SMEM_SZ);
    cudaFuncSetAttribute(mma_gemm<2>, cudaFuncAttributeMaxDynamicSharedMemorySize, SMEM_SZ);

    // CSR build + gather reductions
    zero_counts<<<(N_NODES + 255) / 256, 256>>>();
    count_kernel<<<(N_EDGES + 255) / 256, 256>>>(dst);
    scan_kernel<<<1, 1024>>>();
    fill_kernel<<<(N_EDGES + 255) / 256, 256>>>(dst);
    gather_kernel<<<(N_NODES * 32 + 255) / 256, 256>>>(ea);

    ub_kernel<<<(N_GRAPHS * HIDDEN + 255) / 256, 256>>>(u, W1, b1);
    prep_w<<<(HIDDEN * 144 + NODE_F * 256 + 255) / 256, 256>>>(W1, W2);
    convert_kernel<<<(MPAD * 144 + 255) / 256, 256>>>(x);

    mma_gemm<1><<<dim3(HIDDEN / 128, MTILES), 256, SMEM_SZ>>>(
        Ah, Al, B1h, B1l, nullptr, nullptr, batch, ubT, Hh, Hl, nullptr, K1PAD, HIDDEN);
    mma_gemm<2><<<dim3(NODE_F / 128, MTILES), 256, SMEM_SZ>>>(
        Hh, Hl, B2h, B2l, b2, x, nullptr, nullptr, nullptr, nullptr, out, HIDDEN, NODE_F);
}

// round 9
// speedup vs baseline: 2.7247x; 1.0781x over previous
#include <cuda_runtime.h>
#include <cuda_bf16.h>
#include <cstdint>

#define N_NODES 50000
#define N_EDGES 800000
#define EDGE_F  96
#define NODE_F  256
#define GLOB_F  64
#define HIDDEN  1024
#define N_GRAPHS 8
#define K1PAD   544              // 544 real cols (x|sum|max|mean); 544 = 17*32
#define MTILES  391
#define MPAD    (MTILES*128)     // 50048

// ---------------- device scratch (allocation-free per harness rules) -------
__device__ float g_agg[(size_t)N_NODES*192];       // sum[0:96), max[96:192)
__device__ int   g_cnt[N_NODES];                   // counts, then fill-cursor
__device__ int   g_start[N_NODES + 1];             // CSR offsets (+sentinel)
__device__ int   g_eidx[N_EDGES];
__device__ float g_ub[N_GRAPHS * HIDDEN];          // b1 + u[g] @ W1u
__device__ __nv_bfloat16 g_Ah[(size_t)MPAD*K1PAD];
__device__ __nv_bfloat16 g_Al[(size_t)MPAD*K1PAD];
__device__ __nv_bfloat16 g_Hh[(size_t)MPAD*HIDDEN];
__device__ __nv_bfloat16 g_Hl[(size_t)MPAD*HIDDEN];
__device__ __nv_bfloat16 g_B1h[(size_t)HIDDEN*K1PAD];
__device__ __nv_bfloat16 g_B1l[(size_t)HIDDEN*K1PAD];
__device__ __nv_bfloat16 g_B2h[(size_t)NODE_F*HIDDEN];
__device__ __nv_bfloat16 g_B2l[(size_t)NODE_F*HIDDEN];

// ---------------- PTX helpers ----------------------------------------------
__device__ __forceinline__ uint32_t smem_u32(const void* p) {
    uint32_t a;
    asm("{ .reg .u64 t; cvta.to.shared.u64 t, %1; cvt.u32.u64 %0, t; }" : "=r"(a) : "l"(p));
    return a;
}
#define CPASYNC16(s,g) asm volatile("cp.async.cg.shared.global [%0], [%1], 16;" :: "r"(s), "l"(g))
#define CPCOMMIT()     asm volatile("cp.async.commit_group;" ::: "memory")
#define CPWAIT2()      asm volatile("cp.async.wait_group 2;" ::: "memory")

#define LDSM4(r0,r1,r2,r3,addr) \
    asm volatile("ldmatrix.sync.aligned.m8n8.x4.shared.b16 {%0,%1,%2,%3}, [%4];" \
        : "=r"(r0),"=r"(r1),"=r"(r2),"=r"(r3) : "r"(addr))

#define MMA16816(d,a,b0,b1) \
    asm volatile("mma.sync.aligned.m16n8k16.row.col.f32.bf16.bf16.f32 " \
        "{%0,%1,%2,%3}, {%4,%5,%6,%7}, {%8,%9}, {%0,%1,%2,%3};" \
        : "+f"((d)[0]),"+f"((d)[1]),"+f"((d)[2]),"+f"((d)[3]) \
        : "r"((a)[0]),"r"((a)[1]),"r"((a)[2]),"r"((a)[3]), "r"(b0),"r"(b1))

__device__ __forceinline__ uint32_t pk_hi(float a, float b) {
    return (uint32_t)__bfloat16_as_ushort(__float2bfloat16(a))
         | ((uint32_t)__bfloat16_as_ushort(__float2bfloat16(b)) << 16);
}
__device__ __forceinline__ float bf_res(float v) {   // v - bf16(v)
    return v - __bfloat162float(__float2bfloat16(v));
}

// ---------------- phase 1: CSR build + gather reductions ---------------------
__global__ void zero_counts() {
    int i = blockIdx.x * blockDim.x + threadIdx.x;
    if (i < N_NODES) g_cnt[i] = 0;
}
__global__ void count_kernel(const int* __restrict__ dst) {
    int i = blockIdx.x * blockDim.x + threadIdx.x;
    if (i < N_EDGES) atomicAdd(&g_cnt[dst[i]], 1);
}
// single block, 1024 threads; warp-shuffle scan (2 barriers per 1024-chunk)
__global__ void scan_kernel() {
    __shared__ int wsum[32];
    __shared__ int carry;
    int tid = threadIdx.x;
    int lane = tid & 31, warp = tid >> 5;
    if (tid == 0) carry = 0;
    __syncthreads();
    for (int base = 0; base < N_NODES; base += 1024) {
        int i = base + tid;
        int v = (i < N_NODES) ? g_cnt[i] : 0;
        int inc = v;
#pragma unroll
        for (int off = 1; off < 32; off <<= 1) {
            int t = __shfl_up_sync(0xffffffff, inc, off);
            if (lane >= off) inc += t;
        }
        if (lane == 31) wsum[warp] = inc;
        __syncthreads();
        if (warp == 0) {
            int w = wsum[lane];
#pragma unroll
            for (int off = 1; off < 32; off <<= 1) {
                int t = __shfl_up_sync(0xffffffff, w, off);
                if (lane >= off) w += t;
            }
            wsum[lane] = w;
        }
        __syncthreads();
        int excl = inc - v + (warp > 0 ? wsum[warp - 1] : 0) + carry;
        if (i < N_NODES) {
            g_start[i] = excl;
            g_cnt[i] = 0;                       // reset: becomes fill cursor
        }
        __syncthreads();                        // protect wsum before next iter
        if (tid == 1023) carry = excl + v;
        __syncthreads();
    }
    if (tid == 0) g_start[N_NODES] = N_EDGES;   // sentinel
}
__global__ void fill_kernel(const int* __restrict__ dst) {
    int i = blockIdx.x * blockDim.x + threadIdx.x;
    if (i >= N_EDGES) return;
    int c = dst[i];
    int p = atomicAdd(&g_cnt[c], 1);
    g_eidx[g_start[c] + p] = i;
}
// warp per node, unrolled x8: 24 independent row-loads in flight per warp.
__global__ void gather_kernel(const float* __restrict__ ea) {
    int w = (blockIdx.x * blockDim.x + threadIdx.x) >> 5;
    int lid = threadIdx.x & 31;
    if (w >= N_NODES) return;
    int s = g_start[w], d = g_start[w + 1] - s;
    float ninf = __int_as_float(0xff800000);
    float s0 = 0.f, s1 = 0.f, s2 = 0.f;
    float m0 = ninf, m1 = ninf, m2 = ninf;
    int j = 0;
    for (; j + 8 <= d; j += 8) {
        const float* r[8];
#pragma unroll
        for (int t = 0; t < 8; ++t)
            r[t] = ea + (size_t)g_eidx[s + j + t] * EDGE_F;
        float v0[8], v1[8], v2[8];
#pragma unroll
        for (int t = 0; t < 8; ++t) {
            v0[t] = r[t][lid]; v1[t] = r[t][lid + 32]; v2[t] = r[t][lid + 64];
        }
#pragma unroll
        for (int t = 0; t < 8; ++t) {
            s0 += v0[t]; s1 += v1[t]; s2 += v2[t];
            m0 = fmaxf(m0, v0[t]); m1 = fmaxf(m1, v1[t]); m2 = fmaxf(m2, v2[t]);
        }
    }
    for (; j < d; ++j) {
        const float* r = ea + (size_t)g_eidx[s + j] * EDGE_F;
        float v0 = r[lid], v1 = r[lid + 32], v2 = r[lid + 64];
        s0 += v0; s1 += v1; s2 += v2;
        m0 = fmaxf(m0, v0); m1 = fmaxf(m1, v1); m2 = fmaxf(m2, v2);
    }
    float* o = g_agg + (size_t)w * 192;
    o[lid]       = s0; o[lid + 32]      = s1; o[lid + 64]      = s2;
    o[96 + lid]  = m0; o[96 + lid + 32] = m1; o[96 + lid + 64] = m2;
}

// u-bias table: ub[g][n] = b1[n] + sum_k u[g][k] * W1[544+k][n]
__global__ void ub_kernel(const float* __restrict__ u, const float* __restrict__ W1,
                          const float* __restrict__ b1) {
    int i = blockIdx.x * blockDim.x + threadIdx.x;   // N_GRAPHS*HIDDEN
    if (i >= N_GRAPHS * HIDDEN) return;
    int g = i / HIDDEN, n = i - g * HIDDEN;
    float acc = b1[n];
#pragma unroll 8
    for (int k = 0; k < GLOB_F; ++k)
        acc += u[(size_t)g * GLOB_F + k] * W1[(size_t)(544 + k) * HIDDEN + n];
    g_ub[i] = acc;
}

// compose 544-col MLP input (x|sum|max|mean), bf16-split; rows padded to MPAD
__global__ void convert_kernel(const float* __restrict__ x) {
    int i = blockIdx.x * blockDim.x + threadIdx.x;      // MPAD*136 tasks (4 cols each)
    if (i >= MPAD * 136) return;
    int n = i / 136, q = i - n * 136;
    float v[4] = {0.f, 0.f, 0.f, 0.f};
    if (n < N_NODES) {
        int cnt = g_start[n + 1] - g_start[n];
        float inv = cnt > 0 ? 1.f / (float)cnt : 0.f;
#pragma unroll
        for (int t = 0; t < 4; ++t) {
            int c = q * 4 + t;
            float w;
            if (c < 256)      w = x[(size_t)n * NODE_F + c];
            else if (c < 352) w = g_agg[(size_t)n * 192 + (c - 256)];
            else if (c < 448) w = cnt > 0 ? g_agg[(size_t)n * 192 + 96 + (c - 352)] : 0.f;
            else              w = g_agg[(size_t)n * 192 + (c - 448)] * inv;
            v[t] = w;
        }
    }
    size_t off = (size_t)n * K1PAD + 4 * q;
    *(uint2*)(g_Ah + off) = make_uint2(pk_hi(v[0], v[1]), pk_hi(v[2], v[3]));
    *(uint2*)(g_Al + off) = make_uint2(pk_hi(bf_res(v[0]), bf_res(v[1])),
                                       pk_hi(bf_res(v[2]), bf_res(v[3])));
}

// transpose + split weights: B1[n][k] = W1[k][n] (k<544), B2[n][k] = W2[k][n]
__global__ void prep_w(const float* __restrict__ W1, const float* __restrict__ W2) {
    int i = blockIdx.x * blockDim.x + threadIdx.x;
    const int T1 = HIDDEN * 136;
    if (i < T1) {
        int n = i / 136, q = i - n * 136;
        float v[4];
#pragma unroll
        for (int t = 0; t < 4; ++t)
            v[t] = W1[(size_t)(4 * q + t) * HIDDEN + n];
        size_t off = (size_t)n * K1PAD + 4 * q;
        *(uint2*)(g_B1h + off) = make_uint2(pk_hi(v[0], v[1]), pk_hi(v[2], v[3]));
        *(uint2*)(g_B1l + off) = make_uint2(pk_hi(bf_res(v[0]), bf_res(v[1])),
                                            pk_hi(bf_res(v[2]), bf_res(v[3])));
    } else {
        int j = i - T1;
        if (j >= NODE_F * 256) return;
        int n = j / 256, q = j - n * 256;
        float v[4];
#pragma unroll
        for (int t = 0; t < 4; ++t) v[t] = W2[(size_t)(4 * q + t) * NODE_F + n];
        size_t off = (size_t)n * HIDDEN + 4 * q;
        *(uint2*)(g_B2h + off) = make_uint2(pk_hi(v[0], v[1]), pk_hi(v[2], v[3]));
        *(uint2*)(g_B2l + off) = make_uint2(pk_hi(bf_res(v[0]), bf_res(v[1])),
                                            pk_hi(bf_res(v[2]), bf_res(v[3])));
    }
}

// ---------------- phase 2: warp-mma bf16 3-term GEMM -------------------------
// CTA tile 128x128, BK=32. 8 warps 4(m) x 2(n); warp tile 32x64.
// SMEM stage: Ah Al Bh Bl 8KB each = 32KB; 3 stages = 96KB.
#define STAGE_B 32768

__device__ __forceinline__ void issue_stage(
    uint32_t smemS, const __nv_bfloat16* __restrict__ Ah, const __nv_bfloat16* __restrict__ Al,
    const __nv_bfloat16* __restrict__ Bh, const __nv_bfloat16* __restrict__ Bl,
    int mBase, int cBase, int Kpad, int k0, int tid)
{
#pragma unroll
    for (int j = 0; j < 8; ++j) {
        int t8  = tid + 256 * j;
        int tile = t8 >> 9;
        int idx  = t8 & 511;
        int row  = idx >> 2;
        int ch   = idx & 3;
        uint32_t dst = smemS + tile * 8192 + row * 64 + ((ch ^ (row & 3)) << 4);
        const __nv_bfloat16* src;
        if (tile == 0)      src = Ah + (size_t)(mBase + row) * Kpad + k0 + ch * 8;
        else if (tile == 1) src = Al + (size_t)(mBase + row) * Kpad + k0 + ch * 8;
        else if (tile == 2) src = Bh + (size_t)(cBase + row) * Kpad + k0 + ch * 8;
        else                src = Bl + (size_t)(cBase + row) * Kpad + k0 + ch * 8;
        CPASYNC16(dst, src);
    }
}

template<int EPI>
__global__ __launch_bounds__(256, 2)
void mma_gemm(const __nv_bfloat16* __restrict__ Ah, const __nv_bfloat16* __restrict__ Al,
              const __nv_bfloat16* __restrict__ Bh, const __nv_bfloat16* __restrict__ Bl,
              const float* __restrict__ bias, const float* __restrict__ resid,
              const int* __restrict__ batchArr, const float* __restrict__ ubT,
              __nv_bfloat16* __restrict__ Oh, __nv_bfloat16* __restrict__ Ol,
              float* __restrict__ outF, int Kpad, int ldo)
{
    extern __shared__ char smem[];
    const uint32_t sb = smem_u32(smem);
    const int tid = threadIdx.x;
    const int wid = tid >> 5, lid = tid & 31;
    const int wm = wid >> 1, wn = wid & 1;          // 4x2 warp grid

    const int mBase = blockIdx.y * 128;
    const int cBase = blockIdx.x * 128;
    const int NC = Kpad >> 5;

    const int aRow = wm * 32 + ((lid >> 3) & 1) * 8 + (lid & 7);
    const int aK   = (lid >> 4) & 1;
    const int aB   = aRow * 64, aM = aRow & 3;
    const int bRow = wn * 64 + ((lid >> 4) & 1) * 8 + (lid & 7);
    const int bK   = (lid >> 3) & 1;
    const int bB   = bRow * 64, bM = bRow & 3;

    float acc[2][8][4];
#pragma unroll
    for (int m = 0; m < 2; ++m)
#pragma unroll
        for (int n = 0; n < 8; ++n)
#pragma unroll
            for (int c = 0; c < 4; ++c) acc[m][n][c] = 0.f;

    issue_stage(sb,           Ah, Al, Bh, Bl, mBase, cBase, Kpad, 0,  tid); CPCOMMIT();
    issue_stage(sb + STAGE_B, Ah, Al, Bh, Bl, mBase, cBase, Kpad, 32, tid); CPCOMMIT();

    for (int i = 0; i < NC; ++i) {
        if (i + 2 < NC)
            issue_stage(sb + ((i + 2) % 3) * STAGE_B, Ah, Al, Bh, Bl,
                        mBase, cBase, Kpad, (i + 2) * 32, tid);
        CPCOMMIT();
        CPWAIT2();
        __syncthreads();

        const uint32_t S = sb + (i % 3) * STAGE_B;
#pragma unroll
        for (int ks = 0; ks < 2; ++ks) {
            uint32_t ah[2][4], al[2][4], bh[4][4], bl[4][4];
            const int kcA = ks * 2 + aK;
            const uint32_t offA = ((kcA ^ aM) << 4) + aB;
#pragma unroll
            for (int ms = 0; ms < 2; ++ms) {
                LDSM4(ah[ms][0], ah[ms][1], ah[ms][2], ah[ms][3], S + offA + ms * 1024);
                LDSM4(al[ms][0], al[ms][1], al[ms][2], al[ms][3], S + 8192 + offA + ms * 1024);
            }
            const int kcB = ks * 2 + bK;
            const uint32_t offB = ((kcB ^ bM) << 4) + bB;
#pragma unroll
            for (int nb = 0; nb < 4; ++nb) {
                LDSM4(bh[nb][0], bh[nb][1], bh[nb][2], bh[nb][3], S + 16384 + offB + nb * 1024);
                LDSM4(bl[nb][0], bl[nb][1], bl[nb][2], bl[nb][3], S + 24576 + offB + nb * 1024);
            }
#pragma unroll
            for (int ms = 0; ms < 2; ++ms)
#pragma unroll
                for (int ns = 0; ns < 8; ++ns) {
                    const int nb = ns >> 1, h = (ns & 1) * 2;
                    MMA16816(acc[ms][ns], ah[ms], bh[nb][h], bh[nb][h + 1]);
                    MMA16816(acc[ms][ns], ah[ms], bl[nb][h], bl[nb][h + 1]);
                    MMA16816(acc[ms][ns], al[ms], bh[nb][h], bh[nb][h + 1]);
                }
        }
        __syncthreads();
    }

    // ---------------- epilogue ----------------
    const int l4 = lid >> 2, l2 = (lid & 3) * 2;
#pragma unroll
    for (int ms = 0; ms < 2; ++ms) {
        const int r0 = mBase + wm * 32 + ms * 16 + l4;
        const int r1 = r0 + 8;
        const float* ub0 = nullptr;
        const float* ub1 = nullptr;
        if (EPI == 1) {
            int g0 = (r0 < N_NODES) ? __ldg(&batchArr[r0]) : 0;
            int g1 = (r1 < N_NODES) ? __ldg(&batchArr[r1]) : 0;
            ub0 = ubT + (size_t)g0 * HIDDEN;
            ub1 = ubT + (size_t)g1 * HIDDEN;
        }
#pragma unroll
        for (int ns = 0; ns < 8; ++ns) {
            const int col = cBase + wn * 64 + ns * 8 + l2;
            if (EPI == 1) {
                float v00 = fmaxf(acc[ms][ns][0] + __ldg(&ub0[col]),     0.f);
                float v01 = fmaxf(acc[ms][ns][1] + __ldg(&ub0[col + 1]), 0.f);
                float v10 = fmaxf(acc[ms][ns][2] + __ldg(&ub1[col]),     0.f);
                float v11 = fmaxf(acc[ms][ns][3] + __ldg(&ub1[col + 1]), 0.f);
                *(uint32_t*)(Oh + (size_t)r0 * ldo + col) = pk_hi(v00, v01);
                *(uint32_t*)(Ol + (size_t)r0 * ldo + col) = pk_hi(bf_res(v00), bf_res(v01));
                *(uint32_t*)(Oh + (size_t)r1 * ldo + col) = pk_hi(v10, v11);
                *(uint32_t*)(Ol + (size_t)r1 * ldo + col) = pk_hi(bf_res(v10), bf_res(v11));
            } else {
                const float b0 = __ldg(&bias[col]), b1v = __ldg(&bias[col + 1]);
                if (r0 < N_NODES) {
                    const float* xr = resid + (size_t)r0 * NODE_F + col;
                    *(float2*)(outF + (size_t)r0 * ldo + col) =
                        make_float2(acc[ms][ns][0] + b0 + xr[0],
                                    acc[ms][ns][1] + b1v + xr[1]);
                }
                if (r1 < N_NODES) {
                    const float* xr = resid + (size_t)r1 * NODE_F + col;
                    *(float2*)(outF + (size_t)r1 * ldo + col) =
                        make_float2(acc[ms][ns][2] + b0 + xr[0],
                                    acc[ms][ns][3] + b1v + xr[1]);
                }
            }
        }
    }
}

// ---------------------------------------------------------------------------
extern "C" void kernel_launch(void* const* d_in, const int* in_sizes, int n_in,
                              void* d_out, int out_size) {
    const float* x     = (const float*)d_in[0];
    const float* ea    = (const float*)d_in[1];
    const float* u     = (const float*)d_in[2];
    const float* W1    = (const float*)d_in[3];
    const float* b1    = (const float*)d_in[4];
    const float* W2    = (const float*)d_in[5];
    const float* b2    = (const float*)d_in[6];
    const int*   ei    = (const int*)  d_in[7];   // [2, N_EDGES]; row 1 = dst
    const int*   batch = (const int*)  d_in[8];
    float*       out   = (float*)d_out;
    const int*   dst   = ei + N_EDGES;

    __nv_bfloat16 *Ah, *Al, *Hh, *Hl, *B1h, *B1l, *B2h, *B2l;
    float* ubT;
    cudaGetSymbolAddress((void**)&Ah,  g_Ah);
    cudaGetSymbolAddress((void**)&Al,  g_Al);
    cudaGetSymbolAddress((void**)&Hh,  g_Hh);
    cudaGetSymbolAddress((void**)&Hl,  g_Hl);
    cudaGetSymbolAddress((void**)&B1h, g_B1h);
    cudaGetSymbolAddress((void**)&B1l, g_B1l);
    cudaGetSymbolAddress((void**)&B2h, g_B2h);
    cudaGetSymbolAddress((void**)&B2l, g_B2l);
    cudaGetSymbolAddress((void**)&ubT, g_ub);

    const int SMEM_SZ = 3 * STAGE_B;
    cudaFuncSetAttribute(mma_gemm<1>, cudaFuncAttributeMaxDynamicSharedMemorySize, SMEM_SZ);
    cudaFuncSetAttribute(mma_gemm<2>, cudaFuncAttributeMaxDynamicSharedMemorySize, SMEM_SZ);

    // CSR build + gather reductions
    zero_counts<<<(N_NODES + 255) / 256, 256>>>();
    count_kernel<<<(N_EDGES + 255) / 256, 256>>>(dst);
    scan_kernel<<<1, 1024>>>();
    fill_kernel<<<(N_EDGES + 255) / 256, 256>>>(dst);
    gather_kernel<<<(N_NODES * 32 + 255) / 256, 256>>>(ea);

    ub_kernel<<<(N_GRAPHS * HIDDEN + 255) / 256, 256>>>(u, W1, b1);
    prep_w<<<(HIDDEN * 136 + NODE_F * 256 + 255) / 256, 256>>>(W1, W2);
    convert_kernel<<<(MPAD * 136 + 255) / 256, 256>>>(x);

    mma_gemm<1><<<dim3(HIDDEN / 128, MTILES), 256, SMEM_SZ>>>(
        Ah, Al, B1h, B1l, nullptr, nullptr, batch, ubT, Hh, Hl, nullptr, K1PAD, HIDDEN);
    mma_gemm<2><<<dim3(NODE_F / 128, MTILES), 256, SMEM_SZ>>>(
        Hh, Hl, B2h, B2l, b2, x, nullptr, nullptr, nullptr, nullptr, out, HIDDEN, NODE_F);
}

// round 10
// speedup vs baseline: 2.8125x; 1.0322x over previous
#include <cuda_runtime.h>
#include <cuda_bf16.h>
#include <cstdint>

#define N_NODES 50000
#define N_EDGES 800000
#define EDGE_F  96
#define NODE_F  256
#define GLOB_F  64
#define HIDDEN  1024
#define N_GRAPHS 8
#define K1PAD   544              // 544 real cols (x|sum|max|mean); 544 = 17*32
#define MTILES  391
#define MPAD    (MTILES*128)     // 50048

// ---------------- device scratch (allocation-free per harness rules) -------
__device__ int   g_cnt[N_NODES];                   // counts, then fill-cursor
__device__ int   g_start[N_NODES + 1];             // CSR offsets (+sentinel)
__device__ int   g_eidx[N_EDGES];
__device__ float g_ub[N_GRAPHS * HIDDEN];          // b1 + u[g] @ W1u
__device__ __nv_bfloat16 g_Ah[(size_t)MPAD*K1PAD];
__device__ __nv_bfloat16 g_Al[(size_t)MPAD*K1PAD];
__device__ __nv_bfloat16 g_Hh[(size_t)MPAD*HIDDEN];
__device__ __nv_bfloat16 g_Hl[(size_t)MPAD*HIDDEN];
__device__ __nv_bfloat16 g_B1h[(size_t)HIDDEN*K1PAD];
__device__ __nv_bfloat16 g_B1l[(size_t)HIDDEN*K1PAD];
__device__ __nv_bfloat16 g_B2h[(size_t)NODE_F*HIDDEN];
__device__ __nv_bfloat16 g_B2l[(size_t)NODE_F*HIDDEN];

// ---------------- PTX helpers ----------------------------------------------
__device__ __forceinline__ uint32_t smem_u32(const void* p) {
    uint32_t a;
    asm("{ .reg .u64 t; cvta.to.shared.u64 t, %1; cvt.u32.u64 %0, t; }" : "=r"(a) : "l"(p));
    return a;
}
#define CPASYNC16(s,g) asm volatile("cp.async.cg.shared.global [%0], [%1], 16;" :: "r"(s), "l"(g))
#define CPCOMMIT()     asm volatile("cp.async.commit_group;" ::: "memory")
#define CPWAIT2()      asm volatile("cp.async.wait_group 2;" ::: "memory")

#define LDSM4(r0,r1,r2,r3,addr) \
    asm volatile("ldmatrix.sync.aligned.m8n8.x4.shared.b16 {%0,%1,%2,%3}, [%4];" \
        : "=r"(r0),"=r"(r1),"=r"(r2),"=r"(r3) : "r"(addr))

#define MMA16816(d,a,b0,b1) \
    asm volatile("mma.sync.aligned.m16n8k16.row.col.f32.bf16.bf16.f32 " \
        "{%0,%1,%2,%3}, {%4,%5,%6,%7}, {%8,%9}, {%0,%1,%2,%3};" \
        : "+f"((d)[0]),"+f"((d)[1]),"+f"((d)[2]),"+f"((d)[3]) \
        : "r"((a)[0]),"r"((a)[1]),"r"((a)[2]),"r"((a)[3]), "r"(b0),"r"(b1))

__device__ __forceinline__ uint32_t pk_hi(float a, float b) {
    return (uint32_t)__bfloat16_as_ushort(__float2bfloat16(a))
         | ((uint32_t)__bfloat16_as_ushort(__float2bfloat16(b)) << 16);
}
__device__ __forceinline__ float bf_res(float v) {   // v - bf16(v)
    return v - __bfloat162float(__float2bfloat16(v));
}

// ---------------- phase 1: CSR build + fused gather/compose/split ------------
__global__ void zero_counts() {
    int i = blockIdx.x * blockDim.x + threadIdx.x;
    if (i < N_NODES) g_cnt[i] = 0;
}
__global__ void count_kernel(const int* __restrict__ dst) {
    int i = blockIdx.x * blockDim.x + threadIdx.x;
    if (i < N_EDGES) atomicAdd(&g_cnt[dst[i]], 1);
}
// single block, 1024 threads; warp-shuffle scan (2 barriers per 1024-chunk)
__global__ void scan_kernel() {
    __shared__ int wsum[32];
    __shared__ int carry;
    int tid = threadIdx.x;
    int lane = tid & 31, warp = tid >> 5;
    if (tid == 0) carry = 0;
    __syncthreads();
    for (int base = 0; base < N_NODES; base += 1024) {
        int i = base + tid;
        int v = (i < N_NODES) ? g_cnt[i] : 0;
        int inc = v;
#pragma unroll
        for (int off = 1; off < 32; off <<= 1) {
            int t = __shfl_up_sync(0xffffffff, inc, off);
            if (lane >= off) inc += t;
        }
        if (lane == 31) wsum[warp] = inc;
        __syncthreads();
        if (warp == 0) {
            int w = wsum[lane];
#pragma unroll
            for (int off = 1; off < 32; off <<= 1) {
                int t = __shfl_up_sync(0xffffffff, w, off);
                if (lane >= off) w += t;
            }
            wsum[lane] = w;
        }
        __syncthreads();
        int excl = inc - v + (warp > 0 ? wsum[warp - 1] : 0) + carry;
        if (i < N_NODES) {
            g_start[i] = excl;
            g_cnt[i] = 0;                       // reset: becomes fill cursor
        }
        __syncthreads();                        // protect wsum before next iter
        if (tid == 1023) carry = excl + v;
        __syncthreads();
    }
    if (tid == 0) g_start[N_NODES] = N_EDGES;   // sentinel
}
__global__ void fill_kernel(const int* __restrict__ dst) {
    int i = blockIdx.x * blockDim.x + threadIdx.x;
    if (i >= N_EDGES) return;
    int c = dst[i];
    int p = atomicAdd(&g_cnt[c], 1);
    g_eidx[g_start[c] + p] = i;
}
// warp per node, unrolled x8. Fused: reductions + compose + bf16-split write
// directly into g_Ah/g_Al (x | sum | max | mean layout).
__global__ void gather_kernel(const float* __restrict__ ea, const float* __restrict__ x) {
    int w = (blockIdx.x * blockDim.x + threadIdx.x) >> 5;
    int lid = threadIdx.x & 31;
    if (w >= N_NODES) return;
    int s = g_start[w], d = g_start[w + 1] - s;
    float ninf = __int_as_float(0xff800000);
    float s0 = 0.f, s1 = 0.f, s2 = 0.f;
    float m0 = ninf, m1 = ninf, m2 = ninf;
    int j = 0;
    for (; j + 8 <= d; j += 8) {
        const float* r[8];
#pragma unroll
        for (int t = 0; t < 8; ++t)
            r[t] = ea + (size_t)g_eidx[s + j + t] * EDGE_F;
        float v0[8], v1[8], v2[8];
#pragma unroll
        for (int t = 0; t < 8; ++t) {
            v0[t] = r[t][lid]; v1[t] = r[t][lid + 32]; v2[t] = r[t][lid + 64];
        }
#pragma unroll
        for (int t = 0; t < 8; ++t) {
            s0 += v0[t]; s1 += v1[t]; s2 += v2[t];
            m0 = fmaxf(m0, v0[t]); m1 = fmaxf(m1, v1[t]); m2 = fmaxf(m2, v2[t]);
        }
    }
    for (; j < d; ++j) {
        const float* r = ea + (size_t)g_eidx[s + j] * EDGE_F;
        float v0 = r[lid], v1 = r[lid + 32], v2 = r[lid + 64];
        s0 += v0; s1 += v1; s2 += v2;
        m0 = fmaxf(m0, v0); m1 = fmaxf(m1, v1); m2 = fmaxf(m2, v2);
    }
    if (d == 0) { m0 = m1 = m2 = 0.f; }         // empty segment: max -> 0
    float inv = d > 0 ? 1.f / (float)d : 0.f;

    __nv_bfloat16* Ah = g_Ah + (size_t)w * K1PAD;
    __nv_bfloat16* Al = g_Al + (size_t)w * K1PAD;
#define STSPLIT(c, val) do { float _v = (val); \
    Ah[c] = __float2bfloat16(_v); Al[c] = __float2bfloat16(bf_res(_v)); } while (0)

    STSPLIT(256 + lid, s0); STSPLIT(288 + lid, s1); STSPLIT(320 + lid, s2);
    STSPLIT(352 + lid, m0); STSPLIT(384 + lid, m1); STSPLIT(416 + lid, m2);
    STSPLIT(448 + lid, s0 * inv); STSPLIT(480 + lid, s1 * inv); STSPLIT(512 + lid, s2 * inv);

    const float* xr = x + (size_t)w * NODE_F;
#pragma unroll
    for (int t = 0; t < 8; ++t) {
        int c = t * 32 + lid;
        STSPLIT(c, xr[c]);
    }
#undef STSPLIT
}
// zero the padding rows [N_NODES, MPAD)
__global__ void pad_rows() {
    int i = blockIdx.x * blockDim.x + threadIdx.x;   // (MPAD-N_NODES)*136
    if (i >= (MPAD - N_NODES) * 136) return;
    int n = N_NODES + i / 136, q = i - (i / 136) * 136;
    size_t off = (size_t)n * K1PAD + 4 * q;
    *(uint2*)(g_Ah + off) = make_uint2(0u, 0u);
    *(uint2*)(g_Al + off) = make_uint2(0u, 0u);
}

// u-bias table: ub[g][n] = b1[n] + sum_k u[g][k] * W1[544+k][n]
__global__ void ub_kernel(const float* __restrict__ u, const float* __restrict__ W1,
                          const float* __restrict__ b1) {
    int i = blockIdx.x * blockDim.x + threadIdx.x;   // N_GRAPHS*HIDDEN
    if (i >= N_GRAPHS * HIDDEN) return;
    int g = i / HIDDEN, n = i - g * HIDDEN;
    float acc = b1[n];
#pragma unroll 8
    for (int k = 0; k < GLOB_F; ++k)
        acc += u[(size_t)g * GLOB_F + k] * W1[(size_t)(544 + k) * HIDDEN + n];
    g_ub[i] = acc;
}

// transpose + split weights: B1[n][k] = W1[k][n] (k<544), B2[n][k] = W2[k][n]
__global__ void prep_w(const float* __restrict__ W1, const float* __restrict__ W2) {
    int i = blockIdx.x * blockDim.x + threadIdx.x;
    const int T1 = HIDDEN * 136;
    if (i < T1) {
        int n = i / 136, q = i - n * 136;
        float v[4];
#pragma unroll
        for (int t = 0; t < 4; ++t)
            v[t] = W1[(size_t)(4 * q + t) * HIDDEN + n];
        size_t off = (size_t)n * K1PAD + 4 * q;
        *(uint2*)(g_B1h + off) = make_uint2(pk_hi(v[0], v[1]), pk_hi(v[2], v[3]));
        *(uint2*)(g_B1l + off) = make_uint2(pk_hi(bf_res(v[0]), bf_res(v[1])),
                                            pk_hi(bf_res(v[2]), bf_res(v[3])));
    } else {
        int j = i - T1;
        if (j >= NODE_F * 256) return;
        int n = j / 256, q = j - n * 256;
        float v[4];
#pragma unroll
        for (int t = 0; t < 4; ++t) v[t] = W2[(size_t)(4 * q + t) * NODE_F + n];
        size_t off = (size_t)n * HIDDEN + 4 * q;
        *(uint2*)(g_B2h + off) = make_uint2(pk_hi(v[0], v[1]), pk_hi(v[2], v[3]));
        *(uint2*)(g_B2l + off) = make_uint2(pk_hi(bf_res(v[0]), bf_res(v[1])),
                                            pk_hi(bf_res(v[2]), bf_res(v[3])));
    }
}

// ---------------- phase 2: warp-mma bf16 3-term GEMM -------------------------
// CTA tile 128x128, BK=32. 8 warps 4(m) x 2(n); warp tile 32x64.
// SMEM stage: Ah Al Bh Bl 8KB each = 32KB; 3 stages = 96KB.
#define STAGE_B 32768

__device__ __forceinline__ void issue_stage(
    uint32_t smemS, const __nv_bfloat16* __restrict__ Ah, const __nv_bfloat16* __restrict__ Al,
    const __nv_bfloat16* __restrict__ Bh, const __nv_bfloat16* __restrict__ Bl,
    int mBase, int cBase, int Kpad, int k0, int tid)
{
#pragma unroll
    for (int j = 0; j < 8; ++j) {
        int t8  = tid + 256 * j;
        int tile = t8 >> 9;
        int idx  = t8 & 511;
        int row  = idx >> 2;
        int ch   = idx & 3;
        uint32_t dst = smemS + tile * 8192 + row * 64 + ((ch ^ (row & 3)) << 4);
        const __nv_bfloat16* src;
        if (tile == 0)      src = Ah + (size_t)(mBase + row) * Kpad + k0 + ch * 8;
        else if (tile == 1) src = Al + (size_t)(mBase + row) * Kpad + k0 + ch * 8;
        else if (tile == 2) src = Bh + (size_t)(cBase + row) * Kpad + k0 + ch * 8;
        else                src = Bl + (size_t)(cBase + row) * Kpad + k0 + ch * 8;
        CPASYNC16(dst, src);
    }
}

template<int EPI>
__global__ __launch_bounds__(256, 2)
void mma_gemm(const __nv_bfloat16* __restrict__ Ah, const __nv_bfloat16* __restrict__ Al,
              const __nv_bfloat16* __restrict__ Bh, const __nv_bfloat16* __restrict__ Bl,
              const float* __restrict__ bias, const float* __restrict__ resid,
              const int* __restrict__ batchArr, const float* __restrict__ ubT,
              __nv_bfloat16* __restrict__ Oh, __nv_bfloat16* __restrict__ Ol,
              float* __restrict__ outF, int Kpad, int ldo)
{
    extern __shared__ char smem[];
    const uint32_t sb = smem_u32(smem);
    const int tid = threadIdx.x;
    const int wid = tid >> 5, lid = tid & 31;
    const int wm = wid >> 1, wn = wid & 1;          // 4x2 warp grid

    const int mBase = blockIdx.y * 128;
    const int cBase = blockIdx.x * 128;
    const int NC = Kpad >> 5;

    const int aRow = wm * 32 + ((lid >> 3) & 1) * 8 + (lid & 7);
    const int aK   = (lid >> 4) & 1;
    const int aB   = aRow * 64, aM = aRow & 3;
    const int bRow = wn * 64 + ((lid >> 4) & 1) * 8 + (lid & 7);
    const int bK   = (lid >> 3) & 1;
    const int bB   = bRow * 64, bM = bRow & 3;

    float acc[2][8][4];
#pragma unroll
    for (int m = 0; m < 2; ++m)
#pragma unroll
        for (int n = 0; n < 8; ++n)
#pragma unroll
            for (int c = 0; c < 4; ++c) acc[m][n][c] = 0.f;

    issue_stage(sb,           Ah, Al, Bh, Bl, mBase, cBase, Kpad, 0,  tid); CPCOMMIT();
    issue_stage(sb + STAGE_B, Ah, Al, Bh, Bl, mBase, cBase, Kpad, 32, tid); CPCOMMIT();

    for (int i = 0; i < NC; ++i) {
        if (i + 2 < NC)
            issue_stage(sb + ((i + 2) % 3) * STAGE_B, Ah, Al, Bh, Bl,
                        mBase, cBase, Kpad, (i + 2) * 32, tid);
        CPCOMMIT();
        CPWAIT2();
        __syncthreads();

        const uint32_t S = sb + (i % 3) * STAGE_B;
#pragma unroll
        for (int ks = 0; ks < 2; ++ks) {
            uint32_t ah[2][4], al[2][4], bh[4][4], bl[4][4];
            const int kcA = ks * 2 + aK;
            const uint32_t offA = ((kcA ^ aM) << 4) + aB;
#pragma unroll
            for (int ms = 0; ms < 2; ++ms) {
                LDSM4(ah[ms][0], ah[ms][1], ah[ms][2], ah[ms][3], S + offA + ms * 1024);
                LDSM4(al[ms][0], al[ms][1], al[ms][2], al[ms][3], S + 8192 + offA + ms * 1024);
            }
            const int kcB = ks * 2 + bK;
            const uint32_t offB = ((kcB ^ bM) << 4) + bB;
#pragma unroll
            for (int nb = 0; nb < 4; ++nb) {
                LDSM4(bh[nb][0], bh[nb][1], bh[nb][2], bh[nb][3], S + 16384 + offB + nb * 1024);
                LDSM4(bl[nb][0], bl[nb][1], bl[nb][2], bl[nb][3], S + 24576 + offB + nb * 1024);
            }
#pragma unroll
            for (int ms = 0; ms < 2; ++ms)
#pragma unroll
                for (int ns = 0; ns < 8; ++ns) {
                    const int nb = ns >> 1, h = (ns & 1) * 2;
                    MMA16816(acc[ms][ns], ah[ms], bh[nb][h], bh[nb][h + 1]);
                    MMA16816(acc[ms][ns], ah[ms], bl[nb][h], bl[nb][h + 1]);
                    MMA16816(acc[ms][ns], al[ms], bh[nb][h], bh[nb][h + 1]);
                }
        }
        __syncthreads();
    }

    // ---------------- epilogue ----------------
    const int l4 = lid >> 2, l2 = (lid & 3) * 2;
#pragma unroll
    for (int ms = 0; ms < 2; ++ms) {
        const int r0 = mBase + wm * 32 + ms * 16 + l4;
        const int r1 = r0 + 8;
        const float* ub0 = nullptr;
        const float* ub1 = nullptr;
        if (EPI == 1) {
            int g0 = (r0 < N_NODES) ? __ldg(&batchArr[r0]) : 0;
            int g1 = (r1 < N_NODES) ? __ldg(&batchArr[r1]) : 0;
            ub0 = ubT + (size_t)g0 * HIDDEN;
            ub1 = ubT + (size_t)g1 * HIDDEN;
        }
#pragma unroll
        for (int ns = 0; ns < 8; ++ns) {
            const int col = cBase + wn * 64 + ns * 8 + l2;
            if (EPI == 1) {
                float v00 = fmaxf(acc[ms][ns][0] + __ldg(&ub0[col]),     0.f);
                float v01 = fmaxf(acc[ms][ns][1] + __ldg(&ub0[col + 1]), 0.f);
                float v10 = fmaxf(acc[ms][ns][2] + __ldg(&ub1[col]),     0.f);
                float v11 = fmaxf(acc[ms][ns][3] + __ldg(&ub1[col + 1]), 0.f);
                *(uint32_t*)(Oh + (size_t)r0 * ldo + col) = pk_hi(v00, v01);
                *(uint32_t*)(Ol + (size_t)r0 * ldo + col) = pk_hi(bf_res(v00), bf_res(v01));
                *(uint32_t*)(Oh + (size_t)r1 * ldo + col) = pk_hi(v10, v11);
                *(uint32_t*)(Ol + (size_t)r1 * ldo + col) = pk_hi(bf_res(v10), bf_res(v11));
            } else {
                const float b0 = __ldg(&bias[col]), b1v = __ldg(&bias[col + 1]);
                if (r0 < N_NODES) {
                    const float* xr = resid + (size_t)r0 * NODE_F + col;
                    *(float2*)(outF + (size_t)r0 * ldo + col) =
                        make_float2(acc[ms][ns][0] + b0 + xr[0],
                                    acc[ms][ns][1] + b1v + xr[1]);
                }
                if (r1 < N_NODES) {
                    const float* xr = resid + (size_t)r1 * NODE_F + col;
                    *(float2*)(outF + (size_t)r1 * ldo + col) =
                        make_float2(acc[ms][ns][2] + b0 + xr[0],
                                    acc[ms][ns][3] + b1v + xr[1]);
                }
            }
        }
    }
}

// ---------------------------------------------------------------------------
extern "C" void kernel_launch(void* const* d_in, const int* in_sizes, int n_in,
                              void* d_out, int out_size) {
    const float* x     = (const float*)d_in[0];
    const float* ea    = (const float*)d_in[1];
    const float* u     = (const float*)d_in[2];
    const float* W1    = (const float*)d_in[3];
    const float* b1    = (const float*)d_in[4];
    const float* W2    = (const float*)d_in[5];
    const float* b2    = (const float*)d_in[6];
    const int*   ei    = (const int*)  d_in[7];   // [2, N_EDGES]; row 1 = dst
    const int*   batch = (const int*)  d_in[8];
    float*       out   = (float*)d_out;
    const int*   dst   = ei + N_EDGES;

    __nv_bfloat16 *Ah, *Al, *Hh, *Hl, *B1h, *B1l, *B2h, *B2l;
    float* ubT;
    cudaGetSymbolAddress((void**)&Ah,  g_Ah);
    cudaGetSymbolAddress((void**)&Al,  g_Al);
    cudaGetSymbolAddress((void**)&Hh,  g_Hh);
    cudaGetSymbolAddress((void**)&Hl,  g_Hl);
    cudaGetSymbolAddress((void**)&B1h, g_B1h);
    cudaGetSymbolAddress((void**)&B1l, g_B1l);
    cudaGetSymbolAddress((void**)&B2h, g_B2h);
    cudaGetSymbolAddress((void**)&B2l, g_B2l);
    cudaGetSymbolAddress((void**)&ubT, g_ub);

    const int SMEM_SZ = 3 * STAGE_B;
    cudaFuncSetAttribute(mma_gemm<1>, cudaFuncAttributeMaxDynamicSharedMemorySize, SMEM_SZ);
    cudaFuncSetAttribute(mma_gemm<2>, cudaFuncAttributeMaxDynamicSharedMemorySize, SMEM_SZ);

    // CSR build + fused gather/compose/split
    zero_counts<<<(N_NODES + 255) / 256, 256>>>();
    count_kernel<<<(N_EDGES + 255) / 256, 256>>>(dst);
    scan_kernel<<<1, 1024>>>();
    fill_kernel<<<(N_EDGES + 255) / 256, 256>>>(dst);
    gather_kernel<<<(N_NODES * 32 + 255) / 256, 256>>>(ea, x);
    pad_rows<<<((MPAD - N_NODES) * 136 + 255) / 256, 256>>>();

    ub_kernel<<<(N_GRAPHS * HIDDEN + 255) / 256, 256>>>(u, W1, b1);
    prep_w<<<(HIDDEN * 136 + NODE_F * 256 + 255) / 256, 256>>>(W1, W2);

    mma_gemm<1><<<dim3(HIDDEN / 128, MTILES), 256, SMEM_SZ>>>(
        Ah, Al, B1h, B1l, nullptr, nullptr, batch, ubT, Hh, Hl, nullptr, K1PAD, HIDDEN);
    mma_gemm<2><<<dim3(NODE_F / 128, MTILES), 256, SMEM_SZ>>>(
        Hh, Hl, B2h, B2l, b2, x, nullptr, nullptr, nullptr, nullptr, out, HIDDEN, NODE_F);
}

// round 11
// speedup vs baseline: 3.6541x; 1.2992x over previous
#include <cuda_runtime.h>
#include <cuda_fp16.h>
#include <cstdint>

#define N_NODES 50000
#define N_EDGES 800000
#define EDGE_F  96
#define NODE_F  256
#define GLOB_F  64
#define HIDDEN  1024
#define N_GRAPHS 8
#define K1PAD   544              // x|sum|max|mean = 544 = 17*32
#define MTILES  391
#define MPAD    (MTILES*128)     // 50048

// ---------------- device scratch (allocation-free per harness rules) -------
__device__ int   g_cnt[N_NODES];                   // counts, then fill-cursor
__device__ int   g_start[N_NODES + 1];             // CSR offsets (+sentinel)
__device__ int   g_eidx[N_EDGES];
__device__ float g_ub[N_GRAPHS * HIDDEN];          // b1 + u[g] @ W1u
__device__ __half g_A  [(size_t)MPAD*K1PAD];       // fp16 MLP input
__device__ __half g_H  [(size_t)MPAD*HIDDEN];      // fp16 hidden acts
__device__ __half g_B1h[(size_t)HIDDEN*K1PAD];     // W1^T hi
__device__ __half g_B1l[(size_t)HIDDEN*K1PAD];     // W1^T lo
__device__ __half g_B2h[(size_t)NODE_F*HIDDEN];
__device__ __half g_B2l[(size_t)NODE_F*HIDDEN];

// ---------------- PTX helpers ----------------------------------------------
__device__ __forceinline__ uint32_t smem_u32(const void* p) {
    uint32_t a;
    asm("{ .reg .u64 t; cvta.to.shared.u64 t, %1; cvt.u32.u64 %0, t; }" : "=r"(a) : "l"(p));
    return a;
}
#define CPASYNC16(s,g) asm volatile("cp.async.cg.shared.global [%0], [%1], 16;" :: "r"(s), "l"(g))
#define CPCOMMIT()     asm volatile("cp.async.commit_group;" ::: "memory")
#define CPWAIT2()      asm volatile("cp.async.wait_group 2;" ::: "memory")

#define LDSM4(r0,r1,r2,r3,addr) \
    asm volatile("ldmatrix.sync.aligned.m8n8.x4.shared.b16 {%0,%1,%2,%3}, [%4];" \
        : "=r"(r0),"=r"(r1),"=r"(r2),"=r"(r3) : "r"(addr))

#define MMA16816(d,a,b0,b1) \
    asm volatile("mma.sync.aligned.m16n8k16.row.col.f32.f16.f16.f32 " \
        "{%0,%1,%2,%3}, {%4,%5,%6,%7}, {%8,%9}, {%0,%1,%2,%3};" \
        : "+f"((d)[0]),"+f"((d)[1]),"+f"((d)[2]),"+f"((d)[3]) \
        : "r"((a)[0]),"r"((a)[1]),"r"((a)[2]),"r"((a)[3]), "r"(b0),"r"(b1))

__device__ __forceinline__ uint32_t pk_h(float a, float b) {
    __half2 h = __floats2half2_rn(a, b);
    return *(uint32_t*)&h;
}
__device__ __forceinline__ float h_res(float v) {   // v - fp16(v)
    return v - __half2float(__float2half_rn(v));
}

// ---------------- phase 1: CSR build + fused gather/compose ------------------
__global__ void zero_counts() {
    int i = blockIdx.x * blockDim.x + threadIdx.x;
    if (i < N_NODES) g_cnt[i] = 0;
}
__global__ void count_kernel(const int* __restrict__ dst) {
    int i = blockIdx.x * blockDim.x + threadIdx.x;
    if (i < N_EDGES) atomicAdd(&g_cnt[dst[i]], 1);
}
// single block, 1024 threads; warp-shuffle scan
__global__ void scan_kernel() {
    __shared__ int wsum[32];
    __shared__ int carry;
    int tid = threadIdx.x;
    int lane = tid & 31, warp = tid >> 5;
    if (tid == 0) carry = 0;
    __syncthreads();
    for (int base = 0; base < N_NODES; base += 1024) {
        int i = base + tid;
        int v = (i < N_NODES) ? g_cnt[i] : 0;
        int inc = v;
#pragma unroll
        for (int off = 1; off < 32; off <<= 1) {
            int t = __shfl_up_sync(0xffffffff, inc, off);
            if (lane >= off) inc += t;
        }
        if (lane == 31) wsum[warp] = inc;
        __syncthreads();
        if (warp == 0) {
            int w = wsum[lane];
#pragma unroll
            for (int off = 1; off < 32; off <<= 1) {
                int t = __shfl_up_sync(0xffffffff, w, off);
                if (lane >= off) w += t;
            }
            wsum[lane] = w;
        }
        __syncthreads();
        int excl = inc - v + (warp > 0 ? wsum[warp - 1] : 0) + carry;
        if (i < N_NODES) {
            g_start[i] = excl;
            g_cnt[i] = 0;                       // reset: becomes fill cursor
        }
        __syncthreads();
        if (tid == 1023) carry = excl + v;
        __syncthreads();
    }
    if (tid == 0) g_start[N_NODES] = N_EDGES;   // sentinel
}
__global__ void fill_kernel(const int* __restrict__ dst) {
    int i = blockIdx.x * blockDim.x + threadIdx.x;
    if (i >= N_EDGES) return;
    int c = dst[i];
    int p = atomicAdd(&g_cnt[c], 1);
    g_eidx[g_start[c] + p] = i;
}
// warp per node, unrolled x8; fused compose + fp16 convert into g_A.
__global__ void gather_kernel(const float* __restrict__ ea, const float* __restrict__ x) {
    int w = (blockIdx.x * blockDim.x + threadIdx.x) >> 5;
    int lid = threadIdx.x & 31;
    if (w >= N_NODES) return;
    int s = g_start[w], d = g_start[w + 1] - s;
    float ninf = __int_as_float(0xff800000);
    float s0 = 0.f, s1 = 0.f, s2 = 0.f;
    float m0 = ninf, m1 = ninf, m2 = ninf;
    int j = 0;
    for (; j + 8 <= d; j += 8) {
        const float* r[8];
#pragma unroll
        for (int t = 0; t < 8; ++t)
            r[t] = ea + (size_t)g_eidx[s + j + t] * EDGE_F;
        float v0[8], v1[8], v2[8];
#pragma unroll
        for (int t = 0; t < 8; ++t) {
            v0[t] = r[t][lid]; v1[t] = r[t][lid + 32]; v2[t] = r[t][lid + 64];
        }
#pragma unroll
        for (int t = 0; t < 8; ++t) {
            s0 += v0[t]; s1 += v1[t]; s2 += v2[t];
            m0 = fmaxf(m0, v0[t]); m1 = fmaxf(m1, v1[t]); m2 = fmaxf(m2, v2[t]);
        }
    }
    for (; j < d; ++j) {
        const float* r = ea + (size_t)g_eidx[s + j] * EDGE_F;
        float v0 = r[lid], v1 = r[lid + 32], v2 = r[lid + 64];
        s0 += v0; s1 += v1; s2 += v2;
        m0 = fmaxf(m0, v0); m1 = fmaxf(m1, v1); m2 = fmaxf(m2, v2);
    }
    if (d == 0) { m0 = m1 = m2 = 0.f; }
    float inv = d > 0 ? 1.f / (float)d : 0.f;

    __half* A = g_A + (size_t)w * K1PAD;
    A[256 + lid] = __float2half_rn(s0);
    A[288 + lid] = __float2half_rn(s1);
    A[320 + lid] = __float2half_rn(s2);
    A[352 + lid] = __float2half_rn(m0);
    A[384 + lid] = __float2half_rn(m1);
    A[416 + lid] = __float2half_rn(m2);
    A[448 + lid] = __float2half_rn(s0 * inv);
    A[480 + lid] = __float2half_rn(s1 * inv);
    A[512 + lid] = __float2half_rn(s2 * inv);
    const float* xr = x + (size_t)w * NODE_F;
#pragma unroll
    for (int t = 0; t < 8; ++t) {
        int c = t * 32 + lid;
        A[c] = __float2half_rn(xr[c]);
    }
}
// zero the padding rows [N_NODES, MPAD)
__global__ void pad_rows() {
    int i = blockIdx.x * blockDim.x + threadIdx.x;   // (MPAD-N_NODES)*136 uint2
    if (i >= (MPAD - N_NODES) * 136) return;
    int n = N_NODES + i / 136, q = i - (i / 136) * 136;
    *(uint2*)(g_A + (size_t)n * K1PAD + 4 * q) = make_uint2(0u, 0u);
}

// u-bias table: ub[g][n] = b1[n] + sum_k u[g][k] * W1[544+k][n]
__global__ void ub_kernel(const float* __restrict__ u, const float* __restrict__ W1,
                          const float* __restrict__ b1) {
    int i = blockIdx.x * blockDim.x + threadIdx.x;
    if (i >= N_GRAPHS * HIDDEN) return;
    int g = i / HIDDEN, n = i - g * HIDDEN;
    float acc = b1[n];
#pragma unroll 8
    for (int k = 0; k < GLOB_F; ++k)
        acc += u[(size_t)g * GLOB_F + k] * W1[(size_t)(544 + k) * HIDDEN + n];
    g_ub[i] = acc;
}

// transpose + fp16 hi/lo split weights
__global__ void prep_w(const float* __restrict__ W1, const float* __restrict__ W2) {
    int i = blockIdx.x * blockDim.x + threadIdx.x;
    const int T1 = HIDDEN * 136;
    if (i < T1) {
        int n = i / 136, q = i - n * 136;
        float v[4];
#pragma unroll
        for (int t = 0; t < 4; ++t)
            v[t] = W1[(size_t)(4 * q + t) * HIDDEN + n];
        size_t off = (size_t)n * K1PAD + 4 * q;
        *(uint2*)(g_B1h + off) = make_uint2(pk_h(v[0], v[1]), pk_h(v[2], v[3]));
        *(uint2*)(g_B1l + off) = make_uint2(pk_h(h_res(v[0]), h_res(v[1])),
                                            pk_h(h_res(v[2]), h_res(v[3])));
    } else {
        int j = i - T1;
        if (j >= NODE_F * 256) return;
        int n = j / 256, q = j - n * 256;
        float v[4];
#pragma unroll
        for (int t = 0; t < 4; ++t) v[t] = W2[(size_t)(4 * q + t) * NODE_F + n];
        size_t off = (size_t)n * HIDDEN + 4 * q;
        *(uint2*)(g_B2h + off) = make_uint2(pk_h(v[0], v[1]), pk_h(v[2], v[3]));
        *(uint2*)(g_B2l + off) = make_uint2(pk_h(h_res(v[0]), h_res(v[1])),
                                            pk_h(h_res(v[2]), h_res(v[3])));
    }
}

// ---------------- phase 2: warp-mma fp16 2-term GEMM -------------------------
// CTA tile 128x128, BK=32. 8 warps 4(m) x 2(n); warp tile 32x64.
// SMEM stage: A(8KB) Bh(8KB) Bl(8KB) = 24KB; 3 stages = 72KB.
#define STAGE_B 24576

__device__ __forceinline__ void issue_stage(
    uint32_t smemS, const __half* __restrict__ A,
    const __half* __restrict__ Bh, const __half* __restrict__ Bl,
    int mBase, int cBase, int Kpad, int k0, int tid)
{
#pragma unroll
    for (int j = 0; j < 6; ++j) {
        int t6  = tid + 256 * j;
        int tile = t6 >> 9;
        int idx  = t6 & 511;
        int row  = idx >> 2;
        int ch   = idx & 3;
        uint32_t dst = smemS + tile * 8192 + row * 64 + ((ch ^ (row & 3)) << 4);
        const __half* src;
        if (tile == 0)      src = A  + (size_t)(mBase + row) * Kpad + k0 + ch * 8;
        else if (tile == 1) src = Bh + (size_t)(cBase + row) * Kpad + k0 + ch * 8;
        else                src = Bl + (size_t)(cBase + row) * Kpad + k0 + ch * 8;
        CPASYNC16(dst, src);
    }
}

template<int EPI>
__global__ __launch_bounds__(256, 2)
void mma_gemm(const __half* __restrict__ A,
              const __half* __restrict__ Bh, const __half* __restrict__ Bl,
              const float* __restrict__ bias, const float* __restrict__ resid,
              const int* __restrict__ batchArr, const float* __restrict__ ubT,
              __half* __restrict__ Oh, float* __restrict__ outF, int Kpad, int ldo)
{
    extern __shared__ char smem[];
    const uint32_t sb = smem_u32(smem);
    const int tid = threadIdx.x;
    const int wid = tid >> 5, lid = tid & 31;
    const int wm = wid >> 1, wn = wid & 1;          // 4x2 warp grid

    const int mBase = blockIdx.y * 128;
    const int cBase = blockIdx.x * 128;
    const int NC = Kpad >> 5;

    const int aRow = wm * 32 + ((lid >> 3) & 1) * 8 + (lid & 7);
    const int aK   = (lid >> 4) & 1;
    const int aB   = aRow * 64, aM = aRow & 3;
    const int bRow = wn * 64 + ((lid >> 4) & 1) * 8 + (lid & 7);
    const int bK   = (lid >> 3) & 1;
    const int bB   = bRow * 64, bM = bRow & 3;

    float acc[2][8][4];
#pragma unroll
    for (int m = 0; m < 2; ++m)
#pragma unroll
        for (int n = 0; n < 8; ++n)
#pragma unroll
            for (int c = 0; c < 4; ++c) acc[m][n][c] = 0.f;

    issue_stage(sb,           A, Bh, Bl, mBase, cBase, Kpad, 0,  tid); CPCOMMIT();
    issue_stage(sb + STAGE_B, A, Bh, Bl, mBase, cBase, Kpad, 32, tid); CPCOMMIT();

    for (int i = 0; i < NC; ++i) {
        if (i + 2 < NC)
            issue_stage(sb + ((i + 2) % 3) * STAGE_B, A, Bh, Bl,
                        mBase, cBase, Kpad, (i + 2) * 32, tid);
        CPCOMMIT();
        CPWAIT2();
        __syncthreads();

        const uint32_t S = sb + (i % 3) * STAGE_B;
#pragma unroll
        for (int ks = 0; ks < 2; ++ks) {
            uint32_t ah[2][4], bh[4][4], bl[4][4];
            const int kcA = ks * 2 + aK;
            const uint32_t offA = ((kcA ^ aM) << 4) + aB;
#pragma unroll
            for (int ms = 0; ms < 2; ++ms)
                LDSM4(ah[ms][0], ah[ms][1], ah[ms][2], ah[ms][3], S + offA + ms * 1024);
            const int kcB = ks * 2 + bK;
            const uint32_t offB = ((kcB ^ bM) << 4) + bB;
#pragma unroll
            for (int nb = 0; nb < 4; ++nb) {
                LDSM4(bh[nb][0], bh[nb][1], bh[nb][2], bh[nb][3], S + 8192  + offB + nb * 1024);
                LDSM4(bl[nb][0], bl[nb][1], bl[nb][2], bl[nb][3], S + 16384 + offB + nb * 1024);
            }
#pragma unroll
            for (int ms = 0; ms < 2; ++ms)
#pragma unroll
                for (int ns = 0; ns < 8; ++ns) {
                    const int nb = ns >> 1, h = (ns & 1) * 2;
                    MMA16816(acc[ms][ns], ah[ms], bh[nb][h], bh[nb][h + 1]);
                    MMA16816(acc[ms][ns], ah[ms], bl[nb][h], bl[nb][h + 1]);
                }
        }
        __syncthreads();
    }

    // ---------------- epilogue ----------------
    const int l4 = lid >> 2, l2 = (lid & 3) * 2;
#pragma unroll
    for (int ms = 0; ms < 2; ++ms) {
        const int r0 = mBase + wm * 32 + ms * 16 + l4;
        const int r1 = r0 + 8;
        const float* ub0 = nullptr;
        const float* ub1 = nullptr;
        if (EPI == 1) {
            int g0 = (r0 < N_NODES) ? __ldg(&batchArr[r0]) : 0;
            int g1 = (r1 < N_NODES) ? __ldg(&batchArr[r1]) : 0;
            ub0 = ubT + (size_t)g0 * HIDDEN;
            ub1 = ubT + (size_t)g1 * HIDDEN;
        }
#pragma unroll
        for (int ns = 0; ns < 8; ++ns) {
            const int col = cBase + wn * 64 + ns * 8 + l2;
            if (EPI == 1) {
                float v00 = fmaxf(acc[ms][ns][0] + __ldg(&ub0[col]),     0.f);
                float v01 = fmaxf(acc[ms][ns][1] + __ldg(&ub0[col + 1]), 0.f);
                float v10 = fmaxf(acc[ms][ns][2] + __ldg(&ub1[col]),     0.f);
                float v11 = fmaxf(acc[ms][ns][3] + __ldg(&ub1[col + 1]), 0.f);
                *(uint32_t*)(Oh + (size_t)r0 * ldo + col) = pk_h(v00, v01);
                *(uint32_t*)(Oh + (size_t)r1 * ldo + col) = pk_h(v10, v11);
            } else {
                const float b0 = __ldg(&bias[col]), b1v = __ldg(&bias[col + 1]);
                if (r0 < N_NODES) {
                    const float* xr = resid + (size_t)r0 * NODE_F + col;
                    *(float2*)(outF + (size_t)r0 * ldo + col) =
                        make_float2(acc[ms][ns][0] + b0 + xr[0],
                                    acc[ms][ns][1] + b1v + xr[1]);
                }
                if (r1 < N_NODES) {
                    const float* xr = resid + (size_t)r1 * NODE_F + col;
                    *(float2*)(outF + (size_t)r1 * ldo + col) =
                        make_float2(acc[ms][ns][2] + b0 + xr[0],
                                    acc[ms][ns][3] + b1v + xr[1]);
                }
            }
        }
    }
}

// ---------------------------------------------------------------------------
extern "C" void kernel_launch(void* const* d_in, const int* in_sizes, int n_in,
                              void* d_out, int out_size) {
    const float* x     = (const float*)d_in[0];
    const float* ea    = (const float*)d_in[1];
    const float* u     = (const float*)d_in[2];
    const float* W1    = (const float*)d_in[3];
    const float* b1    = (const float*)d_in[4];
    const float* W2    = (const float*)d_in[5];
    const float* b2    = (const float*)d_in[6];
    const int*   ei    = (const int*)  d_in[7];   // [2, N_EDGES]; row 1 = dst
    const int*   batch = (const int*)  d_in[8];
    float*       out   = (float*)d_out;
    const int*   dst   = ei + N_EDGES;

    __half *A, *H, *B1h, *B1l, *B2h, *B2l;
    float* ubT;
    cudaGetSymbolAddress((void**)&A,   g_A);
    cudaGetSymbolAddress((void**)&H,   g_H);
    cudaGetSymbolAddress((void**)&B1h, g_B1h);
    cudaGetSymbolAddress((void**)&B1l, g_B1l);
    cudaGetSymbolAddress((void**)&B2h, g_B2h);
    cudaGetSymbolAddress((void**)&B2l, g_B2l);
    cudaGetSymbolAddress((void**)&ubT, g_ub);

    const int SMEM_SZ = 3 * STAGE_B;
    cudaFuncSetAttribute(mma_gemm<1>, cudaFuncAttributeMaxDynamicSharedMemorySize, SMEM_SZ);
    cudaFuncSetAttribute(mma_gemm<2>, cudaFuncAttributeMaxDynamicSharedMemorySize, SMEM_SZ);

    // CSR build + fused gather/compose
    zero_counts<<<(N_NODES + 255) / 256, 256>>>();
    count_kernel<<<(N_EDGES + 255) / 256, 256>>>(dst);
    scan_kernel<<<1, 1024>>>();
    fill_kernel<<<(N_EDGES + 255) / 256, 256>>>(dst);
    gather_kernel<<<(N_NODES * 32 + 255) / 256, 256>>>(ea, x);
    pad_rows<<<((MPAD - N_NODES) * 136 + 255) / 256, 256>>>();

    ub_kernel<<<(N_GRAPHS * HIDDEN + 255) / 256, 256>>>(u, W1, b1);
    prep_w<<<(HIDDEN * 136 + NODE_F * 256 + 255) / 256, 256>>>(W1, W2);

    mma_gemm<1><<<dim3(HIDDEN / 128, MTILES), 256, SMEM_SZ>>>(
        A, B1h, B1l, nullptr, nullptr, batch, ubT, H, nullptr, K1PAD, HIDDEN);
    mma_gemm<2><<<dim3(NODE_F / 128, MTILES), 256, SMEM_SZ>>>(
        H, B2h, B2l, b2, x, nullptr, nullptr, nullptr, out, HIDDEN, NODE_F);
}

// round 12
// speedup vs baseline: 5.2291x; 1.4310x over previous
#include <cuda_runtime.h>
#include <cuda_fp16.h>
#include <cstdint>

#define N_NODES 50000
#define N_EDGES 800000
#define EDGE_F  96
#define NODE_F  256
#define GLOB_F  64
#define HIDDEN  1024
#define N_GRAPHS 8
#define K1PAD   544              // x|sum|max|mean = 544 = 17*32
#define MTILES  391
#define MPAD    (MTILES*128)     // 50048

// ---------------- device scratch (allocation-free per harness rules) -------
__device__ int   g_cnt[N_NODES];                   // counts, then fill-cursor
__device__ int   g_start[N_NODES + 1];             // CSR offsets (+sentinel)
__device__ int   g_eidx[N_EDGES];
__device__ float g_ub[N_GRAPHS * HIDDEN];          // b1 + u[g] @ W1u
__device__ __half g_A [(size_t)MPAD*K1PAD];        // fp16 MLP input
__device__ __half g_H [(size_t)MPAD*HIDDEN];       // fp16 hidden acts
__device__ __half g_B1[(size_t)HIDDEN*K1PAD];      // W1^T fp16
__device__ __half g_B2[(size_t)NODE_F*HIDDEN];     // W2^T fp16

// ---------------- PTX helpers ----------------------------------------------
__device__ __forceinline__ uint32_t smem_u32(const void* p) {
    uint32_t a;
    asm("{ .reg .u64 t; cvta.to.shared.u64 t, %1; cvt.u32.u64 %0, t; }" : "=r"(a) : "l"(p));
    return a;
}
#define CPASYNC16(s,g) asm volatile("cp.async.cg.shared.global [%0], [%1], 16;" :: "r"(s), "l"(g))
#define CPCOMMIT()     asm volatile("cp.async.commit_group;" ::: "memory")
#define CPWAIT2()      asm volatile("cp.async.wait_group 2;" ::: "memory")

#define LDSM4(r0,r1,r2,r3,addr) \
    asm volatile("ldmatrix.sync.aligned.m8n8.x4.shared.b16 {%0,%1,%2,%3}, [%4];" \
        : "=r"(r0),"=r"(r1),"=r"(r2),"=r"(r3) : "r"(addr))

#define MMA16816(d,a,b0,b1) \
    asm volatile("mma.sync.aligned.m16n8k16.row.col.f32.f16.f16.f32 " \
        "{%0,%1,%2,%3}, {%4,%5,%6,%7}, {%8,%9}, {%0,%1,%2,%3};" \
        : "+f"((d)[0]),"+f"((d)[1]),"+f"((d)[2]),"+f"((d)[3]) \
        : "r"((a)[0]),"r"((a)[1]),"r"((a)[2]),"r"((a)[3]), "r"(b0),"r"(b1))

__device__ __forceinline__ uint32_t pk_h(float a, float b) {
    __half2 h = __floats2half2_rn(a, b);
    return *(uint32_t*)&h;
}

// ---------------- phase 1: CSR build + fused gather/compose ------------------
__global__ void zero_counts() {
    int i = blockIdx.x * blockDim.x + threadIdx.x;
    if (i < N_NODES) g_cnt[i] = 0;
}
__global__ void count_kernel(const int* __restrict__ dst) {
    int i = blockIdx.x * blockDim.x + threadIdx.x;
    if (i < N_EDGES) atomicAdd(&g_cnt[dst[i]], 1);
}
// single block, 1024 threads; warp-shuffle scan
__global__ void scan_kernel() {
    __shared__ int wsum[32];
    __shared__ int carry;
    int tid = threadIdx.x;
    int lane = tid & 31, warp = tid >> 5;
    if (tid == 0) carry = 0;
    __syncthreads();
    for (int base = 0; base < N_NODES; base += 1024) {
        int i = base + tid;
        int v = (i < N_NODES) ? g_cnt[i] : 0;
        int inc = v;
#pragma unroll
        for (int off = 1; off < 32; off <<= 1) {
            int t = __shfl_up_sync(0xffffffff, inc, off);
            if (lane >= off) inc += t;
        }
        if (lane == 31) wsum[warp] = inc;
        __syncthreads();
        if (warp == 0) {
            int w = wsum[lane];
#pragma unroll
            for (int off = 1; off < 32; off <<= 1) {
                int t = __shfl_up_sync(0xffffffff, w, off);
                if (lane >= off) w += t;
            }
            wsum[lane] = w;
        }
        __syncthreads();
        int excl = inc - v + (warp > 0 ? wsum[warp - 1] : 0) + carry;
        if (i < N_NODES) {
            g_start[i] = excl;
            g_cnt[i] = 0;                       // reset: becomes fill cursor
        }
        __syncthreads();
        if (tid == 1023) carry = excl + v;
        __syncthreads();
    }
    if (tid == 0) g_start[N_NODES] = N_EDGES;   // sentinel
}
__global__ void fill_kernel(const int* __restrict__ dst) {
    int i = blockIdx.x * blockDim.x + threadIdx.x;
    if (i >= N_EDGES) return;
    int c = dst[i];
    int p = atomicAdd(&g_cnt[c], 1);
    g_eidx[g_start[c] + p] = i;
}
// warp per node, unrolled x8; fused compose + fp16 convert into g_A.
__global__ void gather_kernel(const float* __restrict__ ea, const float* __restrict__ x) {
    int w = (blockIdx.x * blockDim.x + threadIdx.x) >> 5;
    int lid = threadIdx.x & 31;
    if (w >= N_NODES) return;
    int s = g_start[w], d = g_start[w + 1] - s;
    float ninf = __int_as_float(0xff800000);
    float s0 = 0.f, s1 = 0.f, s2 = 0.f;
    float m0 = ninf, m1 = ninf, m2 = ninf;
    int j = 0;
    for (; j + 8 <= d; j += 8) {
        const float* r[8];
#pragma unroll
        for (int t = 0; t < 8; ++t)
            r[t] = ea + (size_t)g_eidx[s + j + t] * EDGE_F;
        float v0[8], v1[8], v2[8];
#pragma unroll
        for (int t = 0; t < 8; ++t) {
            v0[t] = r[t][lid]; v1[t] = r[t][lid + 32]; v2[t] = r[t][lid + 64];
        }
#pragma unroll
        for (int t = 0; t < 8; ++t) {
            s0 += v0[t]; s1 += v1[t]; s2 += v2[t];
            m0 = fmaxf(m0, v0[t]); m1 = fmaxf(m1, v1[t]); m2 = fmaxf(m2, v2[t]);
        }
    }
    for (; j < d; ++j) {
        const float* r = ea + (size_t)g_eidx[s + j] * EDGE_F;
        float v0 = r[lid], v1 = r[lid + 32], v2 = r[lid + 64];
        s0 += v0; s1 += v1; s2 += v2;
        m0 = fmaxf(m0, v0); m1 = fmaxf(m1, v1); m2 = fmaxf(m2, v2);
    }
    if (d == 0) { m0 = m1 = m2 = 0.f; }
    float inv = d > 0 ? 1.f / (float)d : 0.f;

    __half* A = g_A + (size_t)w * K1PAD;
    A[256 + lid] = __float2half_rn(s0);
    A[288 + lid] = __float2half_rn(s1);
    A[320 + lid] = __float2half_rn(s2);
    A[352 + lid] = __float2half_rn(m0);
    A[384 + lid] = __float2half_rn(m1);
    A[416 + lid] = __float2half_rn(m2);
    A[448 + lid] = __float2half_rn(s0 * inv);
    A[480 + lid] = __float2half_rn(s1 * inv);
    A[512 + lid] = __float2half_rn(s2 * inv);
    const float* xr = x + (size_t)w * NODE_F;
#pragma unroll
    for (int t = 0; t < 8; ++t) {
        int c = t * 32 + lid;
        A[c] = __float2half_rn(xr[c]);
    }
}
// zero the padding rows [N_NODES, MPAD)
__global__ void pad_rows() {
    int i = blockIdx.x * blockDim.x + threadIdx.x;   // (MPAD-N_NODES)*136 uint2
    if (i >= (MPAD - N_NODES) * 136) return;
    int n = N_NODES + i / 136, q = i - (i / 136) * 136;
    *(uint2*)(g_A + (size_t)n * K1PAD + 4 * q) = make_uint2(0u, 0u);
}

// u-bias table: ub[g][n] = b1[n] + sum_k u[g][k] * W1[544+k][n]
__global__ void ub_kernel(const float* __restrict__ u, const float* __restrict__ W1,
                          const float* __restrict__ b1) {
    int i = blockIdx.x * blockDim.x + threadIdx.x;
    if (i >= N_GRAPHS * HIDDEN) return;
    int g = i / HIDDEN, n = i - g * HIDDEN;
    float acc = b1[n];
#pragma unroll 8
    for (int k = 0; k < GLOB_F; ++k)
        acc += u[(size_t)g * GLOB_F + k] * W1[(size_t)(544 + k) * HIDDEN + n];
    g_ub[i] = acc;
}

// transpose + fp16 convert weights
__global__ void prep_w(const float* __restrict__ W1, const float* __restrict__ W2) {
    int i = blockIdx.x * blockDim.x + threadIdx.x;
    const int T1 = HIDDEN * 136;
    if (i < T1) {
        int n = i / 136, q = i - n * 136;
        float v[4];
#pragma unroll
        for (int t = 0; t < 4; ++t)
            v[t] = W1[(size_t)(4 * q + t) * HIDDEN + n];
        *(uint2*)(g_B1 + (size_t)n * K1PAD + 4 * q) =
            make_uint2(pk_h(v[0], v[1]), pk_h(v[2], v[3]));
    } else {
        int j = i - T1;
        if (j >= NODE_F * 256) return;
        int n = j / 256, q = j - n * 256;
        float v[4];
#pragma unroll
        for (int t = 0; t < 4; ++t) v[t] = W2[(size_t)(4 * q + t) * NODE_F + n];
        *(uint2*)(g_B2 + (size_t)n * HIDDEN + 4 * q) =
            make_uint2(pk_h(v[0], v[1]), pk_h(v[2], v[3]));
    }
}

// ---------------- phase 2: warp-mma fp16 GEMM --------------------------------
// CTA tile 128x128, BK=32. 8 warps 4(m) x 2(n); warp tile 32x64.
// SMEM stage: A(8KB) B(8KB) = 16KB; 3 stages = 48KB.
#define STAGE_B 16384

__device__ __forceinline__ void issue_stage(
    uint32_t smemS, const __half* __restrict__ A, const __half* __restrict__ B,
    int mBase, int cBase, int Kpad, int k0, int tid)
{
#pragma unroll
    for (int j = 0; j < 4; ++j) {
        int t4  = tid + 256 * j;
        int tile = t4 >> 9;
        int idx  = t4 & 511;
        int row  = idx >> 2;
        int ch   = idx & 3;
        uint32_t dst = smemS + tile * 8192 + row * 64 + ((ch ^ (row & 3)) << 4);
        const __half* src = (tile == 0)
            ? A + (size_t)(mBase + row) * Kpad + k0 + ch * 8
            : B + (size_t)(cBase + row) * Kpad + k0 + ch * 8;
        CPASYNC16(dst, src);
    }
}

template<int EPI>
__global__ __launch_bounds__(256, 2)
void mma_gemm(const __half* __restrict__ A, const __half* __restrict__ B,
              const float* __restrict__ bias, const float* __restrict__ resid,
              const int* __restrict__ batchArr, const float* __restrict__ ubT,
              __half* __restrict__ Oh, float* __restrict__ outF, int Kpad, int ldo)
{
    extern __shared__ char smem[];
    const uint32_t sb = smem_u32(smem);
    const int tid = threadIdx.x;
    const int wid = tid >> 5, lid = tid & 31;
    const int wm = wid >> 1, wn = wid & 1;          // 4x2 warp grid

    const int mBase = blockIdx.y * 128;
    const int cBase = blockIdx.x * 128;
    const int NC = Kpad >> 5;

    const int aRow = wm * 32 + ((lid >> 3) & 1) * 8 + (lid & 7);
    const int aK   = (lid >> 4) & 1;
    const int aB   = aRow * 64, aM = aRow & 3;
    const int bRow = wn * 64 + ((lid >> 4) & 1) * 8 + (lid & 7);
    const int bK   = (lid >> 3) & 1;
    const int bB   = bRow * 64, bM = bRow & 3;

    float acc[2][8][4];
#pragma unroll
    for (int m = 0; m < 2; ++m)
#pragma unroll
        for (int n = 0; n < 8; ++n)
#pragma unroll
            for (int c = 0; c < 4; ++c) acc[m][n][c] = 0.f;

    issue_stage(sb,           A, B, mBase, cBase, Kpad, 0,  tid); CPCOMMIT();
    issue_stage(sb + STAGE_B, A, B, mBase, cBase, Kpad, 32, tid); CPCOMMIT();

    for (int i = 0; i < NC; ++i) {
        if (i + 2 < NC)
            issue_stage(sb + ((i + 2) % 3) * STAGE_B, A, B,
                        mBase, cBase, Kpad, (i + 2) * 32, tid);
        CPCOMMIT();
        CPWAIT2();
        __syncthreads();

        const uint32_t S = sb + (i % 3) * STAGE_B;
#pragma unroll
        for (int ks = 0; ks < 2; ++ks) {
            uint32_t ah[2][4], bh[4][4];
            const int kcA = ks * 2 + aK;
            const uint32_t offA = ((kcA ^ aM) << 4) + aB;
#pragma unroll
            for (int ms = 0; ms < 2; ++ms)
                LDSM4(ah[ms][0], ah[ms][1], ah[ms][2], ah[ms][3], S + offA + ms * 1024);
            const int kcB = ks * 2 + bK;
            const uint32_t offB = ((kcB ^ bM) << 4) + bB;
#pragma unroll
            for (int nb = 0; nb < 4; ++nb)
                LDSM4(bh[nb][0], bh[nb][1], bh[nb][2], bh[nb][3], S + 8192 + offB + nb * 1024);
#pragma unroll
            for (int ms = 0; ms < 2; ++ms)
#pragma unroll
                for (int ns = 0; ns < 8; ++ns) {
                    const int nb = ns >> 1, h = (ns & 1) * 2;
                    MMA16816(acc[ms][ns], ah[ms], bh[nb][h], bh[nb][h + 1]);
                }
        }
        __syncthreads();
    }

    // ---------------- epilogue ----------------
    const int l4 = lid >> 2, l2 = (lid & 3) * 2;
#pragma unroll
    for (int ms = 0; ms < 2; ++ms) {
        const int r0 = mBase + wm * 32 + ms * 16 + l4;
        const int r1 = r0 + 8;
        const float* ub0 = nullptr;
        const float* ub1 = nullptr;
        if (EPI == 1) {
            int g0 = (r0 < N_NODES) ? __ldg(&batchArr[r0]) : 0;
            int g1 = (r1 < N_NODES) ? __ldg(&batchArr[r1]) : 0;
            ub0 = ubT + (size_t)g0 * HIDDEN;
            ub1 = ubT + (size_t)g1 * HIDDEN;
        }
#pragma unroll
        for (int ns = 0; ns < 8; ++ns) {
            const int col = cBase + wn * 64 + ns * 8 + l2;
            if (EPI == 1) {
                float v00 = fmaxf(acc[ms][ns][0] + __ldg(&ub0[col]),     0.f);
                float v01 = fmaxf(acc[ms][ns][1] + __ldg(&ub0[col + 1]), 0.f);
                float v10 = fmaxf(acc[ms][ns][2] + __ldg(&ub1[col]),     0.f);
                float v11 = fmaxf(acc[ms][ns][3] + __ldg(&ub1[col + 1]), 0.f);
                *(uint32_t*)(Oh + (size_t)r0 * ldo + col) = pk_h(v00, v01);
                *(uint32_t*)(Oh + (size_t)r1 * ldo + col) = pk_h(v10, v11);
            } else {
                const float b0 = __ldg(&bias[col]), b1v = __ldg(&bias[col + 1]);
                if (r0 < N_NODES) {
                    const float* xr = resid + (size_t)r0 * NODE_F + col;
                    *(float2*)(outF + (size_t)r0 * ldo + col) =
                        make_float2(acc[ms][ns][0] + b0 + xr[0],
                                    acc[ms][ns][1] + b1v + xr[1]);
                }
                if (r1 < N_NODES) {
                    const float* xr = resid + (size_t)r1 * NODE_F + col;
                    *(float2*)(outF + (size_t)r1 * ldo + col) =
                        make_float2(acc[ms][ns][2] + b0 + xr[0],
                                    acc[ms][ns][3] + b1v + xr[1]);
                }
            }
        }
    }
}

// ---------------------------------------------------------------------------
extern "C" void kernel_launch(void* const* d_in, const int* in_sizes, int n_in,
                              void* d_out, int out_size) {
    const float* x     = (const float*)d_in[0];
    const float* ea    = (const float*)d_in[1];
    const float* u     = (const float*)d_in[2];
    const float* W1    = (const float*)d_in[3];
    const float* b1    = (const float*)d_in[4];
    const float* W2    = (const float*)d_in[5];
    const float* b2    = (const float*)d_in[6];
    const int*   ei    = (const int*)  d_in[7];   // [2, N_EDGES]; row 1 = dst
    const int*   batch = (const int*)  d_in[8];
    float*       out   = (float*)d_out;
    const int*   dst   = ei + N_EDGES;

    __half *A, *H, *B1, *B2;
    float* ubT;
    cudaGetSymbolAddress((void**)&A,  g_A);
    cudaGetSymbolAddress((void**)&H,  g_H);
    cudaGetSymbolAddress((void**)&B1, g_B1);
    cudaGetSymbolAddress((void**)&B2, g_B2);
    cudaGetSymbolAddress((void**)&ubT, g_ub);

    const int SMEM_SZ = 3 * STAGE_B;
    cudaFuncSetAttribute(mma_gemm<1>, cudaFuncAttributeMaxDynamicSharedMemorySize, SMEM_SZ);
    cudaFuncSetAttribute(mma_gemm<2>, cudaFuncAttributeMaxDynamicSharedMemorySize, SMEM_SZ);

    // CSR build + fused gather/compose
    zero_counts<<<(N_NODES + 255) / 256, 256>>>();
    count_kernel<<<(N_EDGES + 255) / 256, 256>>>(dst);
    scan_kernel<<<1, 1024>>>();
    fill_kernel<<<(N_EDGES + 255) / 256, 256>>>(dst);
    gather_kernel<<<(N_NODES * 32 + 255) / 256, 256>>>(ea, x);
    pad_rows<<<((MPAD - N_NODES) * 136 + 255) / 256, 256>>>();

    ub_kernel<<<(N_GRAPHS * HIDDEN + 255) / 256, 256>>>(u, W1, b1);
    prep_w<<<(HIDDEN * 136 + NODE_F * 256 + 255) / 256, 256>>>(W1, W2);

    mma_gemm<1><<<dim3(HIDDEN / 128, MTILES), 256, SMEM_SZ>>>(
        A, B1, nullptr, nullptr, batch, ubT, H, nullptr, K1PAD, HIDDEN);
    mma_gemm<2><<<dim3(NODE_F / 128, MTILES), 256, SMEM_SZ>>>(
        H, B2, b2, x, nullptr, nullptr, nullptr, out, HIDDEN, NODE_F);
}

// round 13
// speedup vs baseline: 5.3232x; 1.0180x over previous
#include <cuda_runtime.h>
#include <cuda_fp16.h>
#include <cstdint>

#define N_NODES 50000
#define N_EDGES 800000
#define EDGE_F  96
#define NODE_F  256
#define GLOB_F  64
#define HIDDEN  1024
#define N_GRAPHS 8
#define K1PAD   544              // x|sum|max|mean = 544 = 17*32
#define MTILES  391
#define MPAD    (MTILES*128)     // 50048

// ---------------- device scratch (allocation-free per harness rules) -------
__device__ int   g_cnt[N_NODES];                   // counts, then fill-cursor
__device__ int   g_start[N_NODES + 1];             // CSR offsets (+sentinel)
__device__ int   g_eidx[N_EDGES];
__device__ float g_ub[N_GRAPHS * HIDDEN];          // b1 + u[g] @ W1u
__device__ __half g_A [(size_t)MPAD*K1PAD];        // fp16 MLP input
__device__ __half g_H [(size_t)MPAD*HIDDEN];       // fp16 hidden acts
__device__ __half g_B1[(size_t)HIDDEN*K1PAD];      // W1^T fp16
__device__ __half g_B2[(size_t)NODE_F*HIDDEN];     // W2^T fp16

// ---------------- PTX helpers ----------------------------------------------
__device__ __forceinline__ uint32_t smem_u32(const void* p) {
    uint32_t a;
    asm("{ .reg .u64 t; cvta.to.shared.u64 t, %1; cvt.u32.u64 %0, t; }" : "=r"(a) : "l"(p));
    return a;
}
#define CPASYNC16(s,g) asm volatile("cp.async.cg.shared.global [%0], [%1], 16;" :: "r"(s), "l"(g))
#define CPCOMMIT()     asm volatile("cp.async.commit_group;" ::: "memory")
#define CPWAIT2()      asm volatile("cp.async.wait_group 2;" ::: "memory")

#define LDSM4(r0,r1,r2,r3,addr) \
    asm volatile("ldmatrix.sync.aligned.m8n8.x4.shared.b16 {%0,%1,%2,%3}, [%4];" \
        : "=r"(r0),"=r"(r1),"=r"(r2),"=r"(r3) : "r"(addr))

#define MMA16816(d,a,b0,b1) \
    asm volatile("mma.sync.aligned.m16n8k16.row.col.f32.f16.f16.f32 " \
        "{%0,%1,%2,%3}, {%4,%5,%6,%7}, {%8,%9}, {%0,%1,%2,%3};" \
        : "+f"((d)[0]),"+f"((d)[1]),"+f"((d)[2]),"+f"((d)[3]) \
        : "r"((a)[0]),"r"((a)[1]),"r"((a)[2]),"r"((a)[3]), "r"(b0),"r"(b1))

__device__ __forceinline__ uint32_t pk_h(float a, float b) {
    __half2 h = __floats2half2_rn(a, b);
    return *(uint32_t*)&h;
}

// ---------------- phase 1: CSR build + fused gather/compose ------------------
__global__ void zero_counts() {
    int i = blockIdx.x * blockDim.x + threadIdx.x;
    if (i < N_NODES) g_cnt[i] = 0;
}
__global__ void count_kernel(const int* __restrict__ dst) {
    int i = blockIdx.x * blockDim.x + threadIdx.x;
    if (i < N_EDGES) atomicAdd(&g_cnt[dst[i]], 1);
}
// single block, 1024 threads; warp-shuffle scan
__global__ void scan_kernel() {
    __shared__ int wsum[32];
    __shared__ int carry;
    int tid = threadIdx.x;
    int lane = tid & 31, warp = tid >> 5;
    if (tid == 0) carry = 0;
    __syncthreads();
    for (int base = 0; base < N_NODES; base += 1024) {
        int i = base + tid;
        int v = (i < N_NODES) ? g_cnt[i] : 0;
        int inc = v;
#pragma unroll
        for (int off = 1; off < 32; off <<= 1) {
            int t = __shfl_up_sync(0xffffffff, inc, off);
            if (lane >= off) inc += t;
        }
        if (lane == 31) wsum[warp] = inc;
        __syncthreads();
        if (warp == 0) {
            int w = wsum[lane];
#pragma unroll
            for (int off = 1; off < 32; off <<= 1) {
                int t = __shfl_up_sync(0xffffffff, w, off);
                if (lane >= off) w += t;
            }
            wsum[lane] = w;
        }
        __syncthreads();
        int excl = inc - v + (warp > 0 ? wsum[warp - 1] : 0) + carry;
        if (i < N_NODES) {
            g_start[i] = excl;
            g_cnt[i] = 0;                       // reset: becomes fill cursor
        }
        __syncthreads();
        if (tid == 1023) carry = excl + v;
        __syncthreads();
    }
    if (tid == 0) g_start[N_NODES] = N_EDGES;   // sentinel
}
__global__ void fill_kernel(const int* __restrict__ dst) {
    int i = blockIdx.x * blockDim.x + threadIdx.x;
    if (i >= N_EDGES) return;
    int c = dst[i];
    int p = atomicAdd(&g_cnt[c], 1);
    g_eidx[g_start[c] + p] = i;
}
// warp per node, unrolled x8; fused compose + fp16 convert into g_A.
__global__ void gather_kernel(const float* __restrict__ ea, const float* __restrict__ x) {
    int w = (blockIdx.x * blockDim.x + threadIdx.x) >> 5;
    int lid = threadIdx.x & 31;
    if (w >= N_NODES) return;
    int s = g_start[w], d = g_start[w + 1] - s;
    float ninf = __int_as_float(0xff800000);
    float s0 = 0.f, s1 = 0.f, s2 = 0.f;
    float m0 = ninf, m1 = ninf, m2 = ninf;
    int j = 0;
    for (; j + 8 <= d; j += 8) {
        const float* r[8];
#pragma unroll
        for (int t = 0; t < 8; ++t)
            r[t] = ea + (size_t)g_eidx[s + j + t] * EDGE_F;
        float v0[8], v1[8], v2[8];
#pragma unroll
        for (int t = 0; t < 8; ++t) {
            v0[t] = r[t][lid]; v1[t] = r[t][lid + 32]; v2[t] = r[t][lid + 64];
        }
#pragma unroll
        for (int t = 0; t < 8; ++t) {
            s0 += v0[t]; s1 += v1[t]; s2 += v2[t];
            m0 = fmaxf(m0, v0[t]); m1 = fmaxf(m1, v1[t]); m2 = fmaxf(m2, v2[t]);
        }
    }
    for (; j < d; ++j) {
        const float* r = ea + (size_t)g_eidx[s + j] * EDGE_F;
        float v0 = r[lid], v1 = r[lid + 32], v2 = r[lid + 64];
        s0 += v0; s1 += v1; s2 += v2;
        m0 = fmaxf(m0, v0); m1 = fmaxf(m1, v1); m2 = fmaxf(m2, v2);
    }
    if (d == 0) { m0 = m1 = m2 = 0.f; }
    float inv = d > 0 ? 1.f / (float)d : 0.f;

    __half* A = g_A + (size_t)w * K1PAD;
    A[256 + lid] = __float2half_rn(s0);
    A[288 + lid] = __float2half_rn(s1);
    A[320 + lid] = __float2half_rn(s2);
    A[352 + lid] = __float2half_rn(m0);
    A[384 + lid] = __float2half_rn(m1);
    A[416 + lid] = __float2half_rn(m2);
    A[448 + lid] = __float2half_rn(s0 * inv);
    A[480 + lid] = __float2half_rn(s1 * inv);
    A[512 + lid] = __float2half_rn(s2 * inv);
    const float* xr = x + (size_t)w * NODE_F;
#pragma unroll
    for (int t = 0; t < 8; ++t) {
        int c = t * 32 + lid;
        A[c] = __float2half_rn(xr[c]);
    }
}
// zero the padding rows [N_NODES, MPAD)
__global__ void pad_rows() {
    int i = blockIdx.x * blockDim.x + threadIdx.x;   // (MPAD-N_NODES)*136 uint2
    if (i >= (MPAD - N_NODES) * 136) return;
    int n = N_NODES + i / 136, q = i - (i / 136) * 136;
    *(uint2*)(g_A + (size_t)n * K1PAD + 4 * q) = make_uint2(0u, 0u);
}

// u-bias table: ub[g][n] = b1[n] + sum_k u[g][k] * W1[544+k][n]
__global__ void ub_kernel(const float* __restrict__ u, const float* __restrict__ W1,
                          const float* __restrict__ b1) {
    int i = blockIdx.x * blockDim.x + threadIdx.x;
    if (i >= N_GRAPHS * HIDDEN) return;
    int g = i / HIDDEN, n = i - g * HIDDEN;
    float acc = b1[n];
#pragma unroll 8
    for (int k = 0; k < GLOB_F; ++k)
        acc += u[(size_t)g * GLOB_F + k] * W1[(size_t)(544 + k) * HIDDEN + n];
    g_ub[i] = acc;
}

// coalesced 32x32 smem-tile transpose + fp16 convert of W1 (k<544) and W2.
// Grid: 544 blocks for W1 (17 k-tiles x 32 n-tiles), 256 for W2 (32 x 8).
__global__ void prep_w(const float* __restrict__ W1, const float* __restrict__ W2) {
    __shared__ float tile[32][33];
    int bx = blockIdx.x;
    int tx = threadIdx.x & 31, ty = threadIdx.x >> 5;   // 32 x 8
    if (bx < 544) {
        int k0 = (bx % 17) * 32, n0 = (bx / 17) * 32;
#pragma unroll
        for (int i = 0; i < 4; ++i)
            tile[ty + 8 * i][tx] = W1[(size_t)(k0 + ty + 8 * i) * HIDDEN + n0 + tx];
        __syncthreads();
#pragma unroll
        for (int i = 0; i < 4; ++i)
            g_B1[(size_t)(n0 + ty + 8 * i) * K1PAD + k0 + tx] =
                __float2half_rn(tile[tx][ty + 8 * i]);
    } else {
        int b2 = bx - 544;
        int k0 = (b2 % 32) * 32, n0 = (b2 / 32) * 32;
#pragma unroll
        for (int i = 0; i < 4; ++i)
            tile[ty + 8 * i][tx] = W2[(size_t)(k0 + ty + 8 * i) * NODE_F + n0 + tx];
        __syncthreads();
#pragma unroll
        for (int i = 0; i < 4; ++i)
            g_B2[(size_t)(n0 + ty + 8 * i) * HIDDEN + k0 + tx] =
                __float2half_rn(tile[tx][ty + 8 * i]);
    }
}

// ---------------- phase 2: warp-mma fp16 GEMM --------------------------------
// CTA tile 128x128, BK=32. 8 warps 4(m) x 2(n); warp tile 32x64.
// SMEM stage: A(8KB) B(8KB) = 16KB; 3 stages = 48KB.
#define STAGE_B 16384

__device__ __forceinline__ void issue_stage(
    uint32_t smemS, const __half* __restrict__ A, const __half* __restrict__ B,
    int mBase, int cBase, int Kpad, int k0, int tid)
{
#pragma unroll
    for (int j = 0; j < 4; ++j) {
        int t4  = tid + 256 * j;
        int tile = t4 >> 9;
        int idx  = t4 & 511;
        int row  = idx >> 2;
        int ch   = idx & 3;
        uint32_t dst = smemS + tile * 8192 + row * 64 + ((ch ^ (row & 3)) << 4);
        const __half* src = (tile == 0)
            ? A + (size_t)(mBase + row) * Kpad + k0 + ch * 8
            : B + (size_t)(cBase + row) * Kpad + k0 + ch * 8;
        CPASYNC16(dst, src);
    }
}

template<int EPI>
__global__ __launch_bounds__(256, 2)
void mma_gemm(const __half* __restrict__ A, const __half* __restrict__ B,
              const float* __restrict__ bias, const float* __restrict__ resid,
              const int* __restrict__ batchArr, const float* __restrict__ ubT,
              __half* __restrict__ Oh, float* __restrict__ outF, int Kpad, int ldo)
{
    extern __shared__ char smem[];
    const uint32_t sb = smem_u32(smem);
    const int tid = threadIdx.x;
    const int wid = tid >> 5, lid = tid & 31;
    const int wm = wid >> 1, wn = wid & 1;          // 4x2 warp grid

    const int mBase = blockIdx.y * 128;
    const int cBase = blockIdx.x * 128;
    const int NC = Kpad >> 5;

    const int aRow = wm * 32 + ((lid >> 3) & 1) * 8 + (lid & 7);
    const int aK   = (lid >> 4) & 1;
    const int aB   = aRow * 64, aM = aRow & 3;
    const int bRow = wn * 64 + ((lid >> 4) & 1) * 8 + (lid & 7);
    const int bK   = (lid >> 3) & 1;
    const int bB   = bRow * 64, bM = bRow & 3;

    float acc[2][8][4];
#pragma unroll
    for (int m = 0; m < 2; ++m)
#pragma unroll
        for (int n = 0; n < 8; ++n)
#pragma unroll
            for (int c = 0; c < 4; ++c) acc[m][n][c] = 0.f;

    issue_stage(sb,           A, B, mBase, cBase, Kpad, 0,  tid); CPCOMMIT();
    issue_stage(sb + STAGE_B, A, B, mBase, cBase, Kpad, 32, tid); CPCOMMIT();

    for (int i = 0; i < NC; ++i) {
        if (i + 2 < NC)
            issue_stage(sb + ((i + 2) % 3) * STAGE_B, A, B,
                        mBase, cBase, Kpad, (i + 2) * 32, tid);
        CPCOMMIT();
        CPWAIT2();
        __syncthreads();

        const uint32_t S = sb + (i % 3) * STAGE_B;
#pragma unroll
        for (int ks = 0; ks < 2; ++ks) {
            uint32_t ah[2][4], bh[4][4];
            const int kcA = ks * 2 + aK;
            const uint32_t offA = ((kcA ^ aM) << 4) + aB;
#pragma unroll
            for (int ms = 0; ms < 2; ++ms)
                LDSM4(ah[ms][0], ah[ms][1], ah[ms][2], ah[ms][3], S + offA + ms * 1024);
            const int kcB = ks * 2 + bK;
            const uint32_t offB = ((kcB ^ bM) << 4) + bB;
#pragma unroll
            for (int nb = 0; nb < 4; ++nb)
                LDSM4(bh[nb][0], bh[nb][1], bh[nb][2], bh[nb][3], S + 8192 + offB + nb * 1024);
#pragma unroll
            for (int ms = 0; ms < 2; ++ms)
#pragma unroll
                for (int ns = 0; ns < 8; ++ns) {
                    const int nb = ns >> 1, h = (ns & 1) * 2;
                    MMA16816(acc[ms][ns], ah[ms], bh[nb][h], bh[nb][h + 1]);
                }
        }
        __syncthreads();
    }

    // ---------------- epilogue ----------------
    const int l4 = lid >> 2, l2 = (lid & 3) * 2;
#pragma unroll
    for (int ms = 0; ms < 2; ++ms) {
        const int r0 = mBase + wm * 32 + ms * 16 + l4;
        const int r1 = r0 + 8;
        const float* ub0 = nullptr;
        const float* ub1 = nullptr;
        if (EPI == 1) {
            int g0 = (r0 < N_NODES) ? __ldg(&batchArr[r0]) : 0;
            int g1 = (r1 < N_NODES) ? __ldg(&batchArr[r1]) : 0;
            ub0 = ubT + (size_t)g0 * HIDDEN;
            ub1 = ubT + (size_t)g1 * HIDDEN;
        }
#pragma unroll
        for (int ns = 0; ns < 8; ++ns) {
            const int col = cBase + wn * 64 + ns * 8 + l2;
            if (EPI == 1) {
                float v00 = fmaxf(acc[ms][ns][0] + __ldg(&ub0[col]),     0.f);
                float v01 = fmaxf(acc[ms][ns][1] + __ldg(&ub0[col + 1]), 0.f);
                float v10 = fmaxf(acc[ms][ns][2] + __ldg(&ub1[col]),     0.f);
                float v11 = fmaxf(acc[ms][ns][3] + __ldg(&ub1[col + 1]), 0.f);
                *(uint32_t*)(Oh + (size_t)r0 * ldo + col) = pk_h(v00, v01);
                *(uint32_t*)(Oh + (size_t)r1 * ldo + col) = pk_h(v10, v11);
            } else {
                const float b0 = __ldg(&bias[col]), b1v = __ldg(&bias[col + 1]);
                if (r0 < N_NODES) {
                    const float* xr = resid + (size_t)r0 * NODE_F + col;
                    *(float2*)(outF + (size_t)r0 * ldo + col) =
                        make_float2(acc[ms][ns][0] + b0 + xr[0],
                                    acc[ms][ns][1] + b1v + xr[1]);
                }
                if (r1 < N_NODES) {
                    const float* xr = resid + (size_t)r1 * NODE_F + col;
                    *(float2*)(outF + (size_t)r1 * ldo + col) =
                        make_float2(acc[ms][ns][2] + b0 + xr[0],
                                    acc[ms][ns][3] + b1v + xr[1]);
                }
            }
        }
    }
}

// ---------------------------------------------------------------------------
extern "C" void kernel_launch(void* const* d_in, const int* in_sizes, int n_in,
                              void* d_out, int out_size) {
    const float* x     = (const float*)d_in[0];
    const float* ea    = (const float*)d_in[1];
    const float* u     = (const float*)d_in[2];
    const float* W1    = (const float*)d_in[3];
    const float* b1    = (const float*)d_in[4];
    const float* W2    = (const float*)d_in[5];
    const float* b2    = (const float*)d_in[6];
    const int*   ei    = (const int*)  d_in[7];   // [2, N_EDGES]; row 1 = dst
    const int*   batch = (const int*)  d_in[8];
    float*       out   = (float*)d_out;
    const int*   dst   = ei + N_EDGES;

    __half *A, *H, *B1, *B2;
    float* ubT;
    cudaGetSymbolAddress((void**)&A,  g_A);
    cudaGetSymbolAddress((void**)&H,  g_H);
    cudaGetSymbolAddress((void**)&B1, g_B1);
    cudaGetSymbolAddress((void**)&B2, g_B2);
    cudaGetSymbolAddress((void**)&ubT, g_ub);

    const int SMEM_SZ = 3 * STAGE_B;
    cudaFuncSetAttribute(mma_gemm<1>, cudaFuncAttributeMaxDynamicSharedMemorySize, SMEM_SZ);
    cudaFuncSetAttribute(mma_gemm<2>, cudaFuncAttributeMaxDynamicSharedMemorySize, SMEM_SZ);

    // Fork: weight-prep branch (independent of edges) runs on s1 while the
    // CSR chain runs on the main stream; join before GEMM1.
    cudaStream_t s1;
    cudaStreamCreateWithFlags(&s1, cudaStreamNonBlocking);
    cudaEvent_t evFork, evJoin;
    cudaEventCreateWithFlags(&evFork, cudaEventDisableTiming);
    cudaEventCreateWithFlags(&evJoin, cudaEventDisableTiming);

    cudaEventRecord(evFork, 0);
    cudaStreamWaitEvent(s1, evFork, 0);
    ub_kernel<<<(N_GRAPHS * HIDDEN + 255) / 256, 256, 0, s1>>>(u, W1, b1);
    prep_w<<<544 + 256, 256, 0, s1>>>(W1, W2);
    pad_rows<<<((MPAD - N_NODES) * 136 + 255) / 256, 256, 0, s1>>>();
    cudaEventRecord(evJoin, s1);

    // CSR build + fused gather/compose (main stream)
    zero_counts<<<(N_NODES + 255) / 256, 256>>>();
    count_kernel<<<(N_EDGES + 255) / 256, 256>>>(dst);
    scan_kernel<<<1, 1024>>>();
    fill_kernel<<<(N_EDGES + 255) / 256, 256>>>(dst);
    gather_kernel<<<(N_NODES * 32 + 255) / 256, 256>>>(ea, x);

    cudaStreamWaitEvent(0, evJoin, 0);

    mma_gemm<1><<<dim3(HIDDEN / 128, MTILES), 256, SMEM_SZ>>>(
        A, B1, nullptr, nullptr, batch, ubT, H, nullptr, K1PAD, HIDDEN);
    mma_gemm<2><<<dim3(NODE_F / 128, MTILES), 256, SMEM_SZ>>>(
        H, B2, b2, x, nullptr, nullptr, nullptr, out, HIDDEN, NODE_F);

    cudaEventDestroy(evFork);
    cudaEventDestroy(evJoin);
    cudaStreamDestroy(s1);
}